// round 2
// baseline (speedup 1.0000x reference)
#include <cuda_runtime.h>
#include <math.h>

#define BB   16384
#define HH   256
#define G4   1024      // 4 fused gate blocks * 256
#define STEPS 120
#define OUT_ 31
#define YSTRIDE (STEPS*OUT_)   // 3720

#define BM 64
#define BN 64
#define KT 16

// ---- device scratch (no allocs allowed) ----
__device__ float g_W4t [HH*G4];   // [k][j] combined weights for steps >=1 (transposed, K-major rows)
__device__ float g_W4zt[HH*G4];   // [k][j] step-0 variant (x=0): r/z use Whh only, i_n block = 0
__device__ float g_b4  [G4];      // fused biases
__device__ float g_hA  [BB*HH];
__device__ float g_hB  [BB*HH];

// Build combined weight matrices + biases.
// j = g*256 + c, g in {0:r, 1:z, 2:i_n, 3:h_n}
__global__ void prep_kernel(const float* __restrict__ Wih, const float* __restrict__ Whh,
                            const float* __restrict__ bih, const float* __restrict__ bhh)
{
    int idx = blockIdx.x * blockDim.x + threadIdx.x;   // over 256*1024
    if (idx < HH * G4) {
        int k = idx / G4;
        int j = idx % G4;
        int g = j >> 8;
        int c = j & 255;
        float w, wz;
        if (g == 0)      { float a = Wih[c*HH + k],        b = Whh[c*HH + k];        w = a + b; wz = b; }
        else if (g == 1) { float a = Wih[(256+c)*HH + k],  b = Whh[(256+c)*HH + k];  w = a + b; wz = b; }
        else if (g == 2) { w = Wih[(512+c)*HH + k];  wz = 0.f; }
        else             { w = Whh[(512+c)*HH + k];  wz = w;  }
        g_W4t [idx] = w;
        g_W4zt[idx] = wz;
    }
    if (idx < G4) {
        int g = idx >> 8, c = idx & 255;
        float b;
        if (g == 0)      b = bih[c]       + bhh[c];
        else if (g == 1) b = bih[256+c]   + bhh[256+c];
        else if (g == 2) b = bih[512+c];
        else             b = bhh[512+c];
        g_b4[idx] = b;
    }
}

// One GRU step. Each block: BM=64 batch rows x BN=64 hidden cols, 4 gate accumulators
// per (row,col). blockIdx.y==0 blocks additionally compute y_{step-1} from h_in.
__global__ void __launch_bounds__(256)
gru_step_kernel(const float* __restrict__ h_in, float* __restrict__ h_out,
                const float* __restrict__ W4t,  const float* __restrict__ b4,
                const float* __restrict__ Wout, const float* __restrict__ bout,
                float* __restrict__ y, int step)
{
    __shared__ float smem[8192];          // 32 KB: main phase 5120 floats, y phase 31*264=8184
    float* hs = smem;                     // [KT][BM]  (transposed h tile)
    float* ws = smem + KT*BM;             // [4][KT][BN]

    const int tid  = threadIdx.x;
    const int row0 = blockIdx.x * BM;
    const int col0 = blockIdx.y * BN;

    const int tx = tid & 15;              // col group  (4 cols)
    const int ty = tid >> 4;              // row group  (4 rows)

    // loader mapping for h tile: thread -> (row lr, float4 slot lq)
    const int lr = tid >> 2;              // 0..63
    const int lq = tid & 3;               // 0..3
    const int h_gbase = (row0 + lr) * HH + lq * 4;

    // loader mapping for weight tile: 4 float4 slots per thread
    int w_gbase[4], w_soff[4];
#pragma unroll
    for (int i = 0; i < 4; i++) {
        int e   = tid + i * 256;          // 0..1023 float4 slots
        int g   = e >> 8;
        int rem = e & 255;
        int kk  = rem >> 4;
        int jf  = rem & 15;
        w_gbase[i] = kk * G4 + g * 256 + col0 + jf * 4;
        w_soff [i] = g * (KT*BN) + kk * BN + jf * 4;
    }

    float acc[4][4][4];
#pragma unroll
    for (int g = 0; g < 4; g++)
#pragma unroll
        for (int i = 0; i < 4; i++)
#pragma unroll
            for (int j = 0; j < 4; j++) acc[g][i][j] = 0.f;

    for (int kt = 0; kt < HH; kt += KT) {
        float4 hv = *reinterpret_cast<const float4*>(&h_in[h_gbase + kt]);
        float4 wv[4];
#pragma unroll
        for (int i = 0; i < 4; i++)
            wv[i] = *reinterpret_cast<const float4*>(&W4t[kt * G4 + w_gbase[i]]);

        __syncthreads();   // previous iteration's reads done
        hs[(lq*4+0)*BM + lr] = hv.x;
        hs[(lq*4+1)*BM + lr] = hv.y;
        hs[(lq*4+2)*BM + lr] = hv.z;
        hs[(lq*4+3)*BM + lr] = hv.w;
#pragma unroll
        for (int i = 0; i < 4; i++)
            *reinterpret_cast<float4*>(&ws[w_soff[i]]) = wv[i];
        __syncthreads();   // tile ready

#pragma unroll
        for (int kk = 0; kk < KT; kk++) {
            float4 a  = *reinterpret_cast<const float4*>(&hs[kk*BM + ty*4]);
            float4 b0 = *reinterpret_cast<const float4*>(&ws[0*(KT*BN) + kk*BN + tx*4]);
            float4 b1 = *reinterpret_cast<const float4*>(&ws[1*(KT*BN) + kk*BN + tx*4]);
            float4 b2 = *reinterpret_cast<const float4*>(&ws[2*(KT*BN) + kk*BN + tx*4]);
            float4 b3 = *reinterpret_cast<const float4*>(&ws[3*(KT*BN) + kk*BN + tx*4]);
            float av[4] = {a.x, a.y, a.z, a.w};
            float bv[4][4] = {{b0.x,b0.y,b0.z,b0.w},{b1.x,b1.y,b1.z,b1.w},
                              {b2.x,b2.y,b2.z,b2.w},{b3.x,b3.y,b3.z,b3.w}};
#pragma unroll
            for (int g = 0; g < 4; g++)
#pragma unroll
                for (int i = 0; i < 4; i++)
#pragma unroll
                    for (int j = 0; j < 4; j++)
                        acc[g][i][j] = fmaf(av[i], bv[g][j], acc[g][i][j]);
        }
    }

    // ---- gates + state update ----
#pragma unroll
    for (int i = 0; i < 4; i++) {
        int r = row0 + ty*4 + i;
        float hn[4];
#pragma unroll
        for (int j = 0; j < 4; j++) {
            int c = col0 + tx*4 + j;
            float ar = acc[0][i][j] + b4[c];
            float az = acc[1][i][j] + b4[256 + c];
            float an = acc[2][i][j] + b4[512 + c];
            float ah = acc[3][i][j] + b4[768 + c];
            float rg = 1.f / (1.f + expf(-ar));
            float zg = 1.f / (1.f + expf(-az));
            float ng = tanhf(an + rg * ah);
            float hp = h_in[r*HH + c];
            hn[j] = (1.f - zg) * ng + zg * hp;
        }
        *reinterpret_cast<float4*>(&h_out[r*HH + col0 + tx*4]) =
            make_float4(hn[0], hn[1], hn[2], hn[3]);
    }

    // ---- fold: y_{step-1} = h_in @ Wout^T + bout (only col-block 0; block-uniform branch) ----
    if (blockIdx.y == 0 && step > 0) {
        __syncthreads();                  // all main-phase smem reads complete
        float* wo = smem;                 // [31][264] padded
        for (int idx = tid; idx < OUT_ * HH; idx += 256) {
            int o = idx >> 8, k = idx & 255;
            wo[o*264 + k] = Wout[o*HH + k];
        }
        __syncthreads();

        int rr = tid >> 2;                // 0..63
        int og = (tid & 3) * 8;           // 0,8,16,24
        const float* hrow = &h_in[(row0 + rr) * HH];
        float accy[8];
#pragma unroll
        for (int oi = 0; oi < 8; oi++) accy[oi] = 0.f;

        for (int k = 0; k < HH; k += 4) {
            float4 hv = *reinterpret_cast<const float4*>(&hrow[k]);
#pragma unroll
            for (int oi = 0; oi < 8; oi++) {
                int o = og + oi;
                if (o < OUT_) {
                    float4 wv = *reinterpret_cast<const float4*>(&wo[o*264 + k]);
                    accy[oi] += hv.x*wv.x + hv.y*wv.y + hv.z*wv.z + hv.w*wv.w;
                }
            }
        }
        int base = (row0 + rr) * YSTRIDE + (step - 1) * OUT_;
#pragma unroll
        for (int oi = 0; oi < 8; oi++) {
            int o = og + oi;
            if (o < OUT_) y[base + o] = accy[oi] + bout[o];
        }
    }
}

// y_119 from the final hidden state
__global__ void __launch_bounds__(256)
out_final_kernel(const float* __restrict__ h, const float* __restrict__ Wout,
                 const float* __restrict__ bout, float* __restrict__ y)
{
    __shared__ float wo[OUT_ * 264];
    const int tid  = threadIdx.x;
    const int row0 = blockIdx.x * BM;

    for (int idx = tid; idx < OUT_ * HH; idx += 256) {
        int o = idx >> 8, k = idx & 255;
        wo[o*264 + k] = Wout[o*HH + k];
    }
    __syncthreads();

    int rr = tid >> 2;
    int og = (tid & 3) * 8;
    const float* hrow = &h[(row0 + rr) * HH];
    float accy[8];
#pragma unroll
    for (int oi = 0; oi < 8; oi++) accy[oi] = 0.f;

    for (int k = 0; k < HH; k += 4) {
        float4 hv = *reinterpret_cast<const float4*>(&hrow[k]);
#pragma unroll
        for (int oi = 0; oi < 8; oi++) {
            int o = og + oi;
            if (o < OUT_) {
                float4 wv = *reinterpret_cast<const float4*>(&wo[o*264 + k]);
                accy[oi] += hv.x*wv.x + hv.y*wv.y + hv.z*wv.z + hv.w*wv.w;
            }
        }
    }
    int base = (row0 + rr) * YSTRIDE + (STEPS - 1) * OUT_;
#pragma unroll
    for (int oi = 0; oi < 8; oi++) {
        int o = og + oi;
        if (o < OUT_) y[base + o] = accy[oi] + bout[o];
    }
}

extern "C" void kernel_launch(void* const* d_in, const int* in_sizes, int n_in,
                              void* d_out, int out_size)
{
    const float* hidden = (const float*)d_in[0];   // [1, B, H]
    const float* Wih    = (const float*)d_in[1];   // [3H, H]
    const float* Whh    = (const float*)d_in[2];   // [3H, H]
    const float* bih    = (const float*)d_in[3];   // [3H]
    const float* bhh    = (const float*)d_in[4];   // [3H]
    const float* Wout   = (const float*)d_in[5];   // [31, H]
    const float* bout   = (const float*)d_in[6];   // [31]
    float* y = (float*)d_out;                      // [B, 120, 31]

    float *pW4t, *pW4zt, *pb4, *phA, *phB;
    cudaGetSymbolAddress((void**)&pW4t,  g_W4t);
    cudaGetSymbolAddress((void**)&pW4zt, g_W4zt);
    cudaGetSymbolAddress((void**)&pb4,   g_b4);
    cudaGetSymbolAddress((void**)&phA,   g_hA);
    cudaGetSymbolAddress((void**)&phB,   g_hB);

    prep_kernel<<<(HH*G4 + 255)/256, 256>>>(Wih, Whh, bih, bhh);

    dim3 grid(BB/BM, HH/BN);   // (256, 4)

    // step 0: x = 0 variant, reads harness input directly
    gru_step_kernel<<<grid, 256>>>(hidden, phA, pW4zt, pb4, Wout, bout, y, 0);

    const float* cur = phA;
    float* nxt = phB;
    for (int t = 1; t < STEPS; t++) {
        gru_step_kernel<<<grid, 256>>>(cur, nxt, pW4t, pb4, Wout, bout, y, t);
        const float* tmp = nxt; nxt = (float*)cur; cur = tmp;
    }
    // after loop, `cur` holds h after step 119
    out_final_kernel<<<BB/BM, 256>>>(cur, Wout, bout, y);
}

// round 4
// speedup vs baseline: 1.4149x; 1.4149x over previous
#include <cuda_runtime.h>
#include <cuda_bf16.h>
#include <math.h>
#include <stdint.h>

#define BB 16384
#define HH 256
#define STEPS 120
#define OUT_ 31
#define YSTRIDE (STEPS*OUT_)

// GEMM tiling: CTA = 128 rows x 256 gate cols (4 gates x 64 hidden cols)
#define ST   40            // smem row stride in bf16 elements (32 data + 8 pad)
#define BUFB 61440u        // bytes per K-stage buffer (Ahi 10240 + Alo 10240 + Bhi 20480 + Blo 20480)
#define AHI_OFF 0u
#define ALO_OFF 10240u
#define BHI_OFF 20480u
#define BLO_OFF 40960u
#define SMEM_ALLOC 133120  // max(2*BUFB=122880, epilogue S 128*260*4=133120)

// ---------------- device scratch (no allocs allowed) ----------------
__device__ __nv_bfloat16 g_Whi [4*HH*HH];   // combined weights [1024 gate rows][256 K], steps>=1
__device__ __nv_bfloat16 g_Wlo [4*HH*HH];
__device__ __nv_bfloat16 g_Whi0[4*HH*HH];   // step-0 variant (x=0)
__device__ __nv_bfloat16 g_Wlo0[4*HH*HH];
__device__ float g_b4[4*HH];                // fused biases [g*256+c]
__device__ float g_hA[BB*HH];
__device__ float g_hB[BB*HH];
__device__ __nv_bfloat16 g_s0hi[BB*HH], g_s0lo[BB*HH];
__device__ __nv_bfloat16 g_s1hi[BB*HH], g_s1lo[BB*HH];

// ---------------- PTX helpers (family-safe: sm_80-era only) ----------------
__device__ __forceinline__ uint32_t smem_u32(const void* p) {
    uint32_t a;
    asm("{ .reg .u64 t; cvta.to.shared.u64 t, %1; cvt.u32.u64 %0, t; }" : "=r"(a) : "l"(p));
    return a;
}
__device__ __forceinline__ void cpa16(uint32_t dst, const void* src) {
    asm volatile("cp.async.cg.shared.global [%0], [%1], 16;" :: "r"(dst), "l"(src) : "memory");
}
__device__ __forceinline__ void ldm4(uint32_t* r, uint32_t addr) {
    asm volatile("ldmatrix.sync.aligned.m8n8.x4.shared.b16 {%0,%1,%2,%3}, [%4];"
                 : "=r"(r[0]), "=r"(r[1]), "=r"(r[2]), "=r"(r[3]) : "r"(addr));
}
__device__ __forceinline__ void mma16816(float* c, const uint32_t* a, const uint32_t* b) {
    asm volatile("mma.sync.aligned.m16n8k16.row.col.f32.bf16.bf16.f32 "
                 "{%0,%1,%2,%3}, {%4,%5,%6,%7}, {%8,%9}, {%0,%1,%2,%3};"
                 : "+f"(c[0]), "+f"(c[1]), "+f"(c[2]), "+f"(c[3])
                 : "r"(a[0]), "r"(a[1]), "r"(a[2]), "r"(a[3]), "r"(b[0]), "r"(b[1]));
}

// ---------------- prep: combined weights, bf16 split ----------------
__global__ void prep_kernel(const float* __restrict__ Wih, const float* __restrict__ Whh,
                            const float* __restrict__ bih, const float* __restrict__ bhh)
{
    int idx = blockIdx.x * blockDim.x + threadIdx.x;    // over 1024*256
    if (idx < 4*HH*HH) {
        int j = idx / HH;      // gate row 0..1023
        int k = idx % HH;
        int g = j >> 8, c = j & 255;
        float w, w0;
        if (g == 0)      { float a = Wih[c*HH+k],       b = Whh[c*HH+k];       w = a + b; w0 = b; }
        else if (g == 1) { float a = Wih[(256+c)*HH+k], b = Whh[(256+c)*HH+k]; w = a + b; w0 = b; }
        else if (g == 2) { w = Wih[(512+c)*HH+k]; w0 = 0.f; }
        else             { w = Whh[(512+c)*HH+k]; w0 = w;  }
        __nv_bfloat16 hi = __float2bfloat16(w);
        g_Whi[idx] = hi;
        g_Wlo[idx] = __float2bfloat16(w - __bfloat162float(hi));
        __nv_bfloat16 hi0 = __float2bfloat16(w0);
        g_Whi0[idx] = hi0;
        g_Wlo0[idx] = __float2bfloat16(w0 - __bfloat162float(hi0));
    }
    if (idx < 4*HH) {
        int g = idx >> 8, c = idx & 255;
        float b;
        if (g == 0)      b = bih[c]     + bhh[c];
        else if (g == 1) b = bih[256+c] + bhh[256+c];
        else if (g == 2) b = bih[512+c];
        else             b = bhh[512+c];
        g_b4[idx] = b;
    }
}

// split h0 (fp32) into bf16 hi/lo
__global__ void split_kernel(const float* __restrict__ h,
                             __nv_bfloat16* __restrict__ hi_, __nv_bfloat16* __restrict__ lo_)
{
    int idx = blockIdx.x * blockDim.x + threadIdx.x;
    if (idx < BB*HH) {
        float v = h[idx];
        __nv_bfloat16 hi = __float2bfloat16(v);
        hi_[idx] = hi;
        lo_[idx] = __float2bfloat16(v - __bfloat162float(hi));
    }
}

// ---------------- main GRU step: mma.sync bf16 3-term split GEMM + fused epilogue ----------------
// grid = (BB/128, HH/64) = (128, 4); 512 threads = 16 warps, warp tile 64x32 (2M x 8N grid)
__global__ void __launch_bounds__(512, 1)
gru_mma_kernel(const __nv_bfloat16* __restrict__ Ahi, const __nv_bfloat16* __restrict__ Alo,
               const __nv_bfloat16* __restrict__ Whi, const __nv_bfloat16* __restrict__ Wlo,
               const float* __restrict__ hprev, float* __restrict__ hout,
               __nv_bfloat16* __restrict__ Ohi, __nv_bfloat16* __restrict__ Olo)
{
    extern __shared__ __align__(16) char dsm[];
    const uint32_t sb = smem_u32(dsm);

    const int tid  = threadIdx.x;
    const int lane = tid & 31;
    const int warp = tid >> 5;
    const int wm   = warp >> 3;        // 0..1  -> m offset wm*64
    const int wn   = warp & 7;         // 0..7  -> n offset wn*32
    const int row0 = blockIdx.x * 128;
    const int col0 = blockIdx.y * 64;

    // ldmatrix per-lane row/k components
    const int aRow  = wm*64 + (lane & 15);
    const int aKoff = (lane >> 4) * 8;
    const int bRow  = wn*32 + (lane >> 4) * 8 + (lane & 7);
    const int bKoff = ((lane >> 3) & 1) * 8;

    // global/smem mapping for stage loads
    const int ar  = tid >> 2, aseg = tid & 3;         // A: 512 chunks of 16B

    float acc[4][4][4];
#pragma unroll
    for (int mt = 0; mt < 4; mt++)
#pragma unroll
        for (int nt = 0; nt < 4; nt++)
#pragma unroll
            for (int q = 0; q < 4; q++) acc[mt][nt][q] = 0.f;

    // stage loader: K-stage s into buffer at byte offset bufoff
    auto load_stage = [&](int s, uint32_t bufoff) {
        const int kb = s * 32;
        {
            uint32_t d = sb + bufoff + (uint32_t)(ar*ST + aseg*8) * 2;
            size_t go = (size_t)(row0 + ar) * HH + kb + aseg*8;
            cpa16(d + AHI_OFF, Ahi + go);
            cpa16(d + ALO_OFF, Alo + go);
        }
#pragma unroll
        for (int i = 0; i < 2; i++) {
            int e = tid + i * 512;
            int n = e >> 2, seg = e & 3;
            int j = ((n >> 6) << 8) + col0 + (n & 63);   // global gate row
            uint32_t d = sb + bufoff + (uint32_t)(n*ST + seg*8) * 2;
            size_t go = (size_t)j * HH + kb + seg*8;
            cpa16(d + BHI_OFF, Whi + go);
            cpa16(d + BLO_OFF, Wlo + go);
        }
    };

    load_stage(0, 0);
    asm volatile("cp.async.commit_group;" ::: "memory");

    for (int s = 0; s < 8; s++) {
        asm volatile("cp.async.wait_group 0;" ::: "memory");
        __syncthreads();
        if (s < 7) {
            load_stage(s + 1, ((s + 1) & 1) * BUFB);
            asm volatile("cp.async.commit_group;" ::: "memory");
        }
        const uint32_t base = sb + (s & 1) * BUFB;

#pragma unroll
        for (int kc = 0; kc < 2; kc++) {
            uint32_t bh[8], bl[8];
#pragma unroll
            for (int p = 0; p < 2; p++) {
                uint32_t baddr = base + BHI_OFF +
                    (uint32_t)((bRow + p*16)*ST + kc*16 + bKoff) * 2;
                ldm4(&bh[p*4], baddr);
                ldm4(&bl[p*4], baddr + (BLO_OFF - BHI_OFF));
            }
#pragma unroll
            for (int mt = 0; mt < 4; mt++) {
                uint32_t aaddr = base +
                    (uint32_t)((aRow + mt*16)*ST + kc*16 + aKoff) * 2;
                uint32_t ah[4], al[4];
                ldm4(ah, aaddr + AHI_OFF);
                ldm4(al, aaddr + ALO_OFF);
#pragma unroll
                for (int nt = 0; nt < 4; nt++) {
                    mma16816(acc[mt][nt], ah, &bh[nt*2]);   // hi*hi
                    mma16816(acc[mt][nt], ah, &bl[nt*2]);   // hi*lo
                    mma16816(acc[mt][nt], al, &bh[nt*2]);   // lo*hi
                }
            }
        }
    }

    // ---- epilogue: acc -> smem [128][260] fp32, then gates + h update ----
    __syncthreads();     // all ldmatrix reads done; smem reusable
    float* S = (float*)dsm;
#pragma unroll
    for (int mt = 0; mt < 4; mt++) {
        int rb = wm*64 + mt*16 + (lane >> 2);
#pragma unroll
        for (int nt = 0; nt < 4; nt++) {
            int cb = wn*32 + nt*8 + (lane & 3)*2;
            *(float2*)&S[rb*260 + cb]       = make_float2(acc[mt][nt][0], acc[mt][nt][1]);
            *(float2*)&S[(rb+8)*260 + cb]   = make_float2(acc[mt][nt][2], acc[mt][nt][3]);
        }
    }
    __syncthreads();

#pragma unroll
    for (int i = 0; i < 4; i++) {
        int e  = tid + i * 512;        // 0..2047 over 128 rows x 16 col-chunks
        int r  = e >> 4;
        int cl = (e & 15) * 4;
        int cg = col0 + cl;
        const float* Sr = &S[r*260];
        float4 vr = *(const float4*)&Sr[cl];
        float4 vz = *(const float4*)&Sr[64 + cl];
        float4 vn = *(const float4*)&Sr[128 + cl];
        float4 vh = *(const float4*)&Sr[192 + cl];
        float ga[4] = {vr.x, vr.y, vr.z, vr.w};
        float gz[4] = {vz.x, vz.y, vz.z, vz.w};
        float gn[4] = {vn.x, vn.y, vn.z, vn.w};
        float gh[4] = {vh.x, vh.y, vh.z, vh.w};

        float4 hp4 = *(const float4*)(hprev + (size_t)(row0 + r)*HH + cg);
        float hp[4] = {hp4.x, hp4.y, hp4.z, hp4.w};

        float hn[4];
#pragma unroll
        for (int j = 0; j < 4; j++) {
            int c = cg + j;
            float arv = ga[j] + g_b4[c];
            float azv = gz[j] + g_b4[256 + c];
            float anv = gn[j] + g_b4[512 + c];
            float ahv = gh[j] + g_b4[768 + c];
            float rg = 1.f / (1.f + __expf(-arv));
            float zg = 1.f / (1.f + __expf(-azv));
            float x  = anv + rg * ahv;
            float t  = __expf(-2.f * fabsf(x));
            float th = (1.f - t) / (1.f + t);
            th = copysignf(th, x);
            hn[j] = (1.f - zg) * th + zg * hp[j];
        }
        *(float4*)(hout + (size_t)(row0 + r)*HH + cg) = make_float4(hn[0], hn[1], hn[2], hn[3]);

        union { uint2 u; __nv_bfloat16 b[4]; } ph, pl;
#pragma unroll
        for (int j = 0; j < 4; j++) {
            __nv_bfloat16 hi = __float2bfloat16(hn[j]);
            ph.b[j] = hi;
            pl.b[j] = __float2bfloat16(hn[j] - __bfloat162float(hi));
        }
        *(uint2*)(Ohi + (size_t)(row0 + r)*HH + cg) = ph.u;
        *(uint2*)(Olo + (size_t)(row0 + r)*HH + cg) = pl.u;
    }
}

// ---------------- per-step output projection (fp32, memory-bound) ----------------
__global__ void __launch_bounds__(256)
out_proj_kernel(const float* __restrict__ h, const float* __restrict__ Wout,
                const float* __restrict__ bout, float* __restrict__ y, int step)
{
    __shared__ float wo[OUT_ * 264];
    const int tid  = threadIdx.x;
    const int row0 = blockIdx.x * 64;

    for (int idx = tid; idx < OUT_ * HH; idx += 256) {
        int o = idx >> 8, k = idx & 255;
        wo[o*264 + k] = Wout[o*HH + k];
    }
    __syncthreads();

    int rr = tid >> 2;
    int og = (tid & 3) * 8;
    const float* hrow = &h[(size_t)(row0 + rr) * HH];
    float accy[8];
#pragma unroll
    for (int oi = 0; oi < 8; oi++) accy[oi] = 0.f;

    for (int k = 0; k < HH; k += 4) {
        float4 hv = *reinterpret_cast<const float4*>(&hrow[k]);
#pragma unroll
        for (int oi = 0; oi < 8; oi++) {
            int o = og + oi;
            if (o < OUT_) {
                float4 wv = *reinterpret_cast<const float4*>(&wo[o*264 + k]);
                accy[oi] += hv.x*wv.x + hv.y*wv.y + hv.z*wv.z + hv.w*wv.w;
            }
        }
    }
    size_t base = (size_t)(row0 + rr) * YSTRIDE + (size_t)step * OUT_;
#pragma unroll
    for (int oi = 0; oi < 8; oi++) {
        int o = og + oi;
        if (o < OUT_) y[base + o] = accy[oi] + bout[o];
    }
}

// ---------------- host ----------------
extern "C" void kernel_launch(void* const* d_in, const int* in_sizes, int n_in,
                              void* d_out, int out_size)
{
    const float* hidden = (const float*)d_in[0];
    const float* Wih    = (const float*)d_in[1];
    const float* Whh    = (const float*)d_in[2];
    const float* bih    = (const float*)d_in[3];
    const float* bhh    = (const float*)d_in[4];
    const float* Wout   = (const float*)d_in[5];
    const float* bout   = (const float*)d_in[6];
    float* y = (float*)d_out;

    __nv_bfloat16 *pWhi, *pWlo, *pWhi0, *pWlo0, *ps0hi, *ps0lo, *ps1hi, *ps1lo;
    float *phA, *phB;
    cudaGetSymbolAddress((void**)&pWhi,  g_Whi);
    cudaGetSymbolAddress((void**)&pWlo,  g_Wlo);
    cudaGetSymbolAddress((void**)&pWhi0, g_Whi0);
    cudaGetSymbolAddress((void**)&pWlo0, g_Wlo0);
    cudaGetSymbolAddress((void**)&ps0hi, g_s0hi);
    cudaGetSymbolAddress((void**)&ps0lo, g_s0lo);
    cudaGetSymbolAddress((void**)&ps1hi, g_s1hi);
    cudaGetSymbolAddress((void**)&ps1lo, g_s1lo);
    cudaGetSymbolAddress((void**)&phA,   g_hA);
    cudaGetSymbolAddress((void**)&phB,   g_hB);

    cudaFuncSetAttribute(gru_mma_kernel, cudaFuncAttributeMaxDynamicSharedMemorySize, SMEM_ALLOC);

    prep_kernel<<<(4*HH*HH + 255)/256, 256>>>(Wih, Whh, bih, bhh);
    split_kernel<<<(BB*HH + 255)/256, 256>>>(hidden, ps0hi, ps0lo);

    dim3 grid(BB/128, HH/64);   // (128, 4)

    // step 0: x = 0 variant weights, h_prev = harness input
    gru_mma_kernel<<<grid, 512, SMEM_ALLOC>>>(ps0hi, ps0lo, pWhi0, pWlo0,
                                              hidden, phA, ps1hi, ps1lo);
    out_proj_kernel<<<BB/64, 256>>>(phA, Wout, bout, y, 0);

    float* hin = phA;  float* hot = phB;
    __nv_bfloat16 *ihi = ps1hi, *ilo = ps1lo, *ohi = ps0hi, *olo = ps0lo;

    for (int t = 1; t < STEPS; t++) {
        gru_mma_kernel<<<grid, 512, SMEM_ALLOC>>>(ihi, ilo, pWhi, pWlo,
                                                  hin, hot, ohi, olo);
        out_proj_kernel<<<BB/64, 256>>>(hot, Wout, bout, y, t);
        float* tf = hin; hin = hot; hot = tf;
        __nv_bfloat16* t1 = ihi; ihi = ohi; ohi = t1;
        __nv_bfloat16* t2 = ilo; ilo = olo; olo = t2;
    }
}

// round 7
// speedup vs baseline: 1.9026x; 1.3447x over previous
#include <cuda_runtime.h>
#include <cuda_bf16.h>
#include <math.h>
#include <stdint.h>

#define BB 16384
#define HH 256
#define STEPS 120
#define OUT_ 31
#define YSTRIDE (STEPS*OUT_)

// GEMM tiling: CTA = 128 rows x 256 gate cols (4 gates x 64 hidden cols)
#define ST   40            // smem row stride in bf16 elements (32 data + 8 pad)
#define BUFB 61440u        // bytes per K-stage buffer (Ahi 10240 + Alo 10240 + Bhi 20480 + Blo 20480)
#define AHI_OFF 0u
#define ALO_OFF 10240u
#define BHI_OFF 20480u
#define BLO_OFF 40960u
#define SMEM_ALLOC 133120  // max(2*BUFB=122880, epilogue S 128*260*4=133120)

// out_proj smem layout: [4 kgroups][31 o][68 floats]
#define WO_OS 68
#define WO_KG (OUT_*WO_OS)   // 2108

// ---------------- device scratch (no allocs allowed) ----------------
__device__ __nv_bfloat16 g_Whi [4*HH*HH];   // combined weights [1024 gate rows][256 K], steps>=1
__device__ __nv_bfloat16 g_Wlo [4*HH*HH];
__device__ __nv_bfloat16 g_Whi0[4*HH*HH];   // step-0 variant (x=0)
__device__ __nv_bfloat16 g_Wlo0[4*HH*HH];
__device__ float g_b4[4*HH];                // fused biases [g*256+c]
__device__ float g_hA[BB*HH];
__device__ float g_hB[BB*HH];
__device__ __nv_bfloat16 g_s0hi[BB*HH], g_s0lo[BB*HH];
__device__ __nv_bfloat16 g_s1hi[BB*HH], g_s1lo[BB*HH];

// ---------------- PTX helpers (family-safe: sm_80-era only) ----------------
__device__ __forceinline__ uint32_t smem_u32(const void* p) {
    uint32_t a;
    asm("{ .reg .u64 t; cvta.to.shared.u64 t, %1; cvt.u32.u64 %0, t; }" : "=r"(a) : "l"(p));
    return a;
}
__device__ __forceinline__ void cpa16(uint32_t dst, const void* src) {
    asm volatile("cp.async.cg.shared.global [%0], [%1], 16;" :: "r"(dst), "l"(src) : "memory");
}
__device__ __forceinline__ void ldm4(uint32_t* r, uint32_t addr) {
    asm volatile("ldmatrix.sync.aligned.m8n8.x4.shared.b16 {%0,%1,%2,%3}, [%4];"
                 : "=r"(r[0]), "=r"(r[1]), "=r"(r[2]), "=r"(r[3]) : "r"(addr));
}
__device__ __forceinline__ void mma16816(float* c, const uint32_t* a, const uint32_t* b) {
    asm volatile("mma.sync.aligned.m16n8k16.row.col.f32.bf16.bf16.f32 "
                 "{%0,%1,%2,%3}, {%4,%5,%6,%7}, {%8,%9}, {%0,%1,%2,%3};"
                 : "+f"(c[0]), "+f"(c[1]), "+f"(c[2]), "+f"(c[3])
                 : "r"(a[0]), "r"(a[1]), "r"(a[2]), "r"(a[3]), "r"(b[0]), "r"(b[1]));
}

// ---------------- prep: combined weights, bf16 split ----------------
__global__ void prep_kernel(const float* __restrict__ Wih, const float* __restrict__ Whh,
                            const float* __restrict__ bih, const float* __restrict__ bhh)
{
    int idx = blockIdx.x * blockDim.x + threadIdx.x;    // over 1024*256
    if (idx < 4*HH*HH) {
        int j = idx / HH;      // gate row 0..1023
        int k = idx % HH;
        int g = j >> 8, c = j & 255;
        float w, w0;
        if (g == 0)      { float a = Wih[c*HH+k],       b = Whh[c*HH+k];       w = a + b; w0 = b; }
        else if (g == 1) { float a = Wih[(256+c)*HH+k], b = Whh[(256+c)*HH+k]; w = a + b; w0 = b; }
        else if (g == 2) { w = Wih[(512+c)*HH+k]; w0 = 0.f; }
        else             { w = Whh[(512+c)*HH+k]; w0 = w;  }
        __nv_bfloat16 hi = __float2bfloat16(w);
        g_Whi[idx] = hi;
        g_Wlo[idx] = __float2bfloat16(w - __bfloat162float(hi));
        __nv_bfloat16 hi0 = __float2bfloat16(w0);
        g_Whi0[idx] = hi0;
        g_Wlo0[idx] = __float2bfloat16(w0 - __bfloat162float(hi0));
    }
    if (idx < 4*HH) {
        int g = idx >> 8, c = idx & 255;
        float b;
        if (g == 0)      b = bih[c]     + bhh[c];
        else if (g == 1) b = bih[256+c] + bhh[256+c];
        else if (g == 2) b = bih[512+c];
        else             b = bhh[512+c];
        g_b4[idx] = b;
    }
}

// split h0 (fp32) into bf16 hi/lo
__global__ void split_kernel(const float* __restrict__ h,
                             __nv_bfloat16* __restrict__ hi_, __nv_bfloat16* __restrict__ lo_)
{
    int idx = blockIdx.x * blockDim.x + threadIdx.x;
    if (idx < BB*HH) {
        float v = h[idx];
        __nv_bfloat16 hi = __float2bfloat16(v);
        hi_[idx] = hi;
        lo_[idx] = __float2bfloat16(v - __bfloat162float(hi));
    }
}

// ---------------- main GRU step: mma.sync bf16 3-term split GEMM + fused epilogue ----------------
// grid = (BB/128, HH/64) = (128, 4); 512 threads = 16 warps, warp tile 64x32 (2M x 8N grid)
__global__ void __launch_bounds__(512, 1)
gru_mma_kernel(const __nv_bfloat16* __restrict__ Ahi, const __nv_bfloat16* __restrict__ Alo,
               const __nv_bfloat16* __restrict__ Whi, const __nv_bfloat16* __restrict__ Wlo,
               const float* __restrict__ hprev, float* __restrict__ hout,
               __nv_bfloat16* __restrict__ Ohi, __nv_bfloat16* __restrict__ Olo)
{
    extern __shared__ __align__(16) char dsm[];
    const uint32_t sb = smem_u32(dsm);

    const int tid  = threadIdx.x;
    const int lane = tid & 31;
    const int warp = tid >> 5;
    const int wm   = warp >> 3;        // 0..1  -> m offset wm*64
    const int wn   = warp & 7;         // 0..7  -> n offset wn*32
    const int row0 = blockIdx.x * 128;
    const int col0 = blockIdx.y * 64;

    // ldmatrix per-lane row/k components
    const int aRow  = wm*64 + (lane & 15);
    const int aKoff = (lane >> 4) * 8;
    const int bRow  = wn*32 + (lane >> 4) * 8 + (lane & 7);
    const int bKoff = ((lane >> 3) & 1) * 8;

    // global/smem mapping for stage loads
    const int ar  = tid >> 2, aseg = tid & 3;         // A: 512 chunks of 16B

    float acc[4][4][4];
#pragma unroll
    for (int mt = 0; mt < 4; mt++)
#pragma unroll
        for (int nt = 0; nt < 4; nt++)
#pragma unroll
            for (int q = 0; q < 4; q++) acc[mt][nt][q] = 0.f;

    // stage loader: K-stage s into buffer at byte offset bufoff
    auto load_stage = [&](int s, uint32_t bufoff) {
        const int kb = s * 32;
        {
            uint32_t d = sb + bufoff + (uint32_t)(ar*ST + aseg*8) * 2;
            size_t go = (size_t)(row0 + ar) * HH + kb + aseg*8;
            cpa16(d + AHI_OFF, Ahi + go);
            cpa16(d + ALO_OFF, Alo + go);
        }
#pragma unroll
        for (int i = 0; i < 2; i++) {
            int e = tid + i * 512;
            int n = e >> 2, seg = e & 3;
            int j = ((n >> 6) << 8) + col0 + (n & 63);   // global gate row
            uint32_t d = sb + bufoff + (uint32_t)(n*ST + seg*8) * 2;
            size_t go = (size_t)j * HH + kb + seg*8;
            cpa16(d + BHI_OFF, Whi + go);
            cpa16(d + BLO_OFF, Wlo + go);
        }
    };

    load_stage(0, 0);
    asm volatile("cp.async.commit_group;" ::: "memory");

    for (int s = 0; s < 8; s++) {
        asm volatile("cp.async.wait_group 0;" ::: "memory");
        __syncthreads();
        if (s < 7) {
            load_stage(s + 1, ((s + 1) & 1) * BUFB);
            asm volatile("cp.async.commit_group;" ::: "memory");
        }
        const uint32_t base = sb + (s & 1) * BUFB;

#pragma unroll
        for (int kc = 0; kc < 2; kc++) {
            uint32_t bh[8], bl[8];
#pragma unroll
            for (int p = 0; p < 2; p++) {
                uint32_t baddr = base + BHI_OFF +
                    (uint32_t)((bRow + p*16)*ST + kc*16 + bKoff) * 2;
                ldm4(&bh[p*4], baddr);
                ldm4(&bl[p*4], baddr + (BLO_OFF - BHI_OFF));
            }
#pragma unroll
            for (int mt = 0; mt < 4; mt++) {
                uint32_t aaddr = base +
                    (uint32_t)((aRow + mt*16)*ST + kc*16 + aKoff) * 2;
                uint32_t ah[4], al[4];
                ldm4(ah, aaddr + AHI_OFF);
                ldm4(al, aaddr + ALO_OFF);
#pragma unroll
                for (int nt = 0; nt < 4; nt++) {
                    mma16816(acc[mt][nt], ah, &bh[nt*2]);   // hi*hi
                    mma16816(acc[mt][nt], ah, &bl[nt*2]);   // hi*lo
                    mma16816(acc[mt][nt], al, &bh[nt*2]);   // lo*hi
                }
            }
        }
    }

    // ---- epilogue: acc -> smem [128][260] fp32, then gates + h update ----
    __syncthreads();     // all ldmatrix reads done; smem reusable
    float* S = (float*)dsm;
#pragma unroll
    for (int mt = 0; mt < 4; mt++) {
        int rb = wm*64 + mt*16 + (lane >> 2);
#pragma unroll
        for (int nt = 0; nt < 4; nt++) {
            int cb = wn*32 + nt*8 + (lane & 3)*2;
            *(float2*)&S[rb*260 + cb]       = make_float2(acc[mt][nt][0], acc[mt][nt][1]);
            *(float2*)&S[(rb+8)*260 + cb]   = make_float2(acc[mt][nt][2], acc[mt][nt][3]);
        }
    }
    __syncthreads();

#pragma unroll
    for (int i = 0; i < 4; i++) {
        int e  = tid + i * 512;        // 0..2047 over 128 rows x 16 col-chunks
        int r  = e >> 4;
        int cl = (e & 15) * 4;
        int cg = col0 + cl;
        const float* Sr = &S[r*260];
        float4 vr = *(const float4*)&Sr[cl];
        float4 vz = *(const float4*)&Sr[64 + cl];
        float4 vn = *(const float4*)&Sr[128 + cl];
        float4 vh = *(const float4*)&Sr[192 + cl];
        float ga[4] = {vr.x, vr.y, vr.z, vr.w};
        float gz[4] = {vz.x, vz.y, vz.z, vz.w};
        float gn[4] = {vn.x, vn.y, vn.z, vn.w};
        float gh[4] = {vh.x, vh.y, vh.z, vh.w};

        float4 hp4 = *(const float4*)(hprev + (size_t)(row0 + r)*HH + cg);
        float hp[4] = {hp4.x, hp4.y, hp4.z, hp4.w};

        float hn[4];
#pragma unroll
        for (int j = 0; j < 4; j++) {
            int c = cg + j;
            float arv = ga[j] + g_b4[c];
            float azv = gz[j] + g_b4[256 + c];
            float anv = gn[j] + g_b4[512 + c];
            float ahv = gh[j] + g_b4[768 + c];
            float rg = 1.f / (1.f + __expf(-arv));
            float zg = 1.f / (1.f + __expf(-azv));
            float x  = anv + rg * ahv;
            float t  = __expf(-2.f * fabsf(x));
            float th = (1.f - t) / (1.f + t);
            th = copysignf(th, x);
            hn[j] = (1.f - zg) * th + zg * hp[j];
        }
        *(float4*)(hout + (size_t)(row0 + r)*HH + cg) = make_float4(hn[0], hn[1], hn[2], hn[3]);

        union { uint2 u; __nv_bfloat16 b[4]; } ph, pl;
#pragma unroll
        for (int j = 0; j < 4; j++) {
            __nv_bfloat16 hi = __float2bfloat16(hn[j]);
            ph.b[j] = hi;
            pl.b[j] = __float2bfloat16(hn[j] - __bfloat162float(hi));
        }
        *(uint2*)(Ohi + (size_t)(row0 + r)*HH + cg) = ph.u;
        *(uint2*)(Olo + (size_t)(row0 + r)*HH + cg) = pl.u;
    }
}

// ---------------- per-step output projection: split-K4 + shfl reduce ----------------
// block = 128 threads = 32 rows (4 lanes per row, 64 K each); grid = BB/32 = 512
__global__ void __launch_bounds__(128)
out_proj_kernel(const float* __restrict__ h, const float* __restrict__ Wout,
                const float* __restrict__ bout, float* __restrict__ y, int step)
{
    __shared__ float wo[4 * WO_KG];   // [kg][o][68] = 33728 B

    const int tid = threadIdx.x;
    for (int idx = tid; idx < OUT_ * HH; idx += 128) {
        int o = idx >> 8, k = idx & 255;
        wo[(k >> 6) * WO_KG + o * WO_OS + (k & 63)] = Wout[idx];
    }
    __syncthreads();

    const int row = blockIdx.x * 32 + (tid >> 2);
    const int kg  = tid & 3;
    const float4* hv4 = (const float4*)(h + (size_t)row * HH + kg * 64);
    const float*  wg  = wo + kg * WO_KG;

    float acc[OUT_];
#pragma unroll
    for (int o = 0; o < OUT_; o++) acc[o] = 0.f;

#pragma unroll 4
    for (int kk = 0; kk < 16; kk++) {
        float4 hv = hv4[kk];
#pragma unroll
        for (int o = 0; o < OUT_; o++) {
            float4 wv = *(const float4*)&wg[o * WO_OS + kk * 4];
            acc[o] = fmaf(hv.x, wv.x, fmaf(hv.y, wv.y, fmaf(hv.z, wv.z, fmaf(hv.w, wv.w, acc[o]))));
        }
    }

#pragma unroll
    for (int o = 0; o < OUT_; o++) {
        acc[o] += __shfl_xor_sync(0xffffffffu, acc[o], 1);
        acc[o] += __shfl_xor_sync(0xffffffffu, acc[o], 2);
    }

    if (kg == 0) {
        size_t base = (size_t)row * YSTRIDE + (size_t)step * OUT_;
#pragma unroll
        for (int o = 0; o < OUT_; o++) y[base + o] = acc[o] + bout[o];
    }
}

// ---------------- host ----------------
extern "C" void kernel_launch(void* const* d_in, const int* in_sizes, int n_in,
                              void* d_out, int out_size)
{
    const float* hidden = (const float*)d_in[0];
    const float* Wih    = (const float*)d_in[1];
    const float* Whh    = (const float*)d_in[2];
    const float* bih    = (const float*)d_in[3];
    const float* bhh    = (const float*)d_in[4];
    const float* Wout   = (const float*)d_in[5];
    const float* bout   = (const float*)d_in[6];
    float* y = (float*)d_out;

    __nv_bfloat16 *pWhi, *pWlo, *pWhi0, *pWlo0, *ps0hi, *ps0lo, *ps1hi, *ps1lo;
    float *phA, *phB;
    cudaGetSymbolAddress((void**)&pWhi,  g_Whi);
    cudaGetSymbolAddress((void**)&pWlo,  g_Wlo);
    cudaGetSymbolAddress((void**)&pWhi0, g_Whi0);
    cudaGetSymbolAddress((void**)&pWlo0, g_Wlo0);
    cudaGetSymbolAddress((void**)&ps0hi, g_s0hi);
    cudaGetSymbolAddress((void**)&ps0lo, g_s0lo);
    cudaGetSymbolAddress((void**)&ps1hi, g_s1hi);
    cudaGetSymbolAddress((void**)&ps1lo, g_s1lo);
    cudaGetSymbolAddress((void**)&phA,   g_hA);
    cudaGetSymbolAddress((void**)&phB,   g_hB);

    cudaFuncSetAttribute(gru_mma_kernel, cudaFuncAttributeMaxDynamicSharedMemorySize, SMEM_ALLOC);

    prep_kernel<<<(4*HH*HH + 255)/256, 256>>>(Wih, Whh, bih, bhh);
    split_kernel<<<(BB*HH + 255)/256, 256>>>(hidden, ps0hi, ps0lo);

    dim3 grid(BB/128, HH/64);   // (128, 4)

    // step 0: x = 0 variant weights, h_prev = harness input
    gru_mma_kernel<<<grid, 512, SMEM_ALLOC>>>(ps0hi, ps0lo, pWhi0, pWlo0,
                                              hidden, phA, ps1hi, ps1lo);
    out_proj_kernel<<<BB/32, 128>>>(phA, Wout, bout, y, 0);

    float* hin = phA;  float* hot = phB;
    __nv_bfloat16 *ihi = ps1hi, *ilo = ps1lo, *ohi = ps0hi, *olo = ps0lo;

    for (int t = 1; t < STEPS; t++) {
        gru_mma_kernel<<<grid, 512, SMEM_ALLOC>>>(ihi, ilo, pWhi, pWlo,
                                                  hin, hot, ohi, olo);
        out_proj_kernel<<<BB/32, 128>>>(hot, Wout, bout, y, t);
        float* tf = hin; hin = hot; hot = tf;
        __nv_bfloat16* t1 = ihi; ihi = ohi; ohi = t1;
        __nv_bfloat16* t2 = ilo; ilo = olo; olo = t2;
    }
}

// round 8
// speedup vs baseline: 2.9371x; 1.5437x over previous
#include <cuda_runtime.h>
#include <cuda_fp16.h>
#include <math.h>
#include <stdint.h>

#define BB 16384
#define HH 256
#define STEPS 120
#define OUT_ 31
#define YSTRIDE (STEPS*OUT_)

// ---- gru GEMM tiling: CTA = 128 rows x 256 gate cols (4 gates x 64 hidden cols) ----
#define ST   40            // smem row stride in halves (32 data + 8 pad)
#define A_OFF   0u
#define BHI_OFF 10240u     // A stage = 128*40*2 = 10240 B
#define BLO_OFF 30720u     // Bhi = 256*40*2 = 20480 B
#define BUFB    51200u     // stage total
#define SMEM_ALLOC 133120  // max(2*BUFB=102400, epilogue S 128*260*4=133120)

// ---- out_proj tiling ----
#define OP_ST 264          // halves per smem row (256 + 8 pad)
#define OPA_OFF 0u
#define OPW_OFF 33792u     // A = 64*264*2
#define OP_SMEM 50688u     // + W 32*264*2 = 16896

// ---------------- device scratch (no allocs allowed) ----------------
__device__ __half g_Whi [4*HH*HH];   // combined gate weights [1024 rows][256 K], steps>=1
__device__ __half g_Wlo [4*HH*HH];
__device__ __half g_Whi0[4*HH*HH];   // step-0 variant (x=0)
__device__ __half g_Wlo0[4*HH*HH];
__device__ __half g_WoutH[32*HH];    // fp16 Wout, row 31 zero-padded
__device__ float g_b4[4*HH];         // fused biases [g*256+c]
__device__ float g_hA[BB*HH];
__device__ float g_hB[BB*HH];
__device__ __half g_s0[BB*HH], g_s1[BB*HH];   // fp16 h state ping-pong

// ---------------- PTX helpers (family-safe: sm_80-era only) ----------------
__device__ __forceinline__ uint32_t smem_u32(const void* p) {
    uint32_t a;
    asm("{ .reg .u64 t; cvta.to.shared.u64 t, %1; cvt.u32.u64 %0, t; }" : "=r"(a) : "l"(p));
    return a;
}
__device__ __forceinline__ void cpa16(uint32_t dst, const void* src) {
    asm volatile("cp.async.cg.shared.global [%0], [%1], 16;" :: "r"(dst), "l"(src) : "memory");
}
__device__ __forceinline__ void ldm4(uint32_t* r, uint32_t addr) {
    asm volatile("ldmatrix.sync.aligned.m8n8.x4.shared.b16 {%0,%1,%2,%3}, [%4];"
                 : "=r"(r[0]), "=r"(r[1]), "=r"(r[2]), "=r"(r[3]) : "r"(addr));
}
__device__ __forceinline__ void mma16816(float* c, const uint32_t* a, const uint32_t* b) {
    asm volatile("mma.sync.aligned.m16n8k16.row.col.f32.f16.f16.f32 "
                 "{%0,%1,%2,%3}, {%4,%5,%6,%7}, {%8,%9}, {%0,%1,%2,%3};"
                 : "+f"(c[0]), "+f"(c[1]), "+f"(c[2]), "+f"(c[3])
                 : "r"(a[0]), "r"(a[1]), "r"(a[2]), "r"(a[3]), "r"(b[0]), "r"(b[1]));
}

// ---------------- prep: combined weights, fp16 split; Wout fp16 ----------------
__global__ void prep_kernel(const float* __restrict__ Wih, const float* __restrict__ Whh,
                            const float* __restrict__ bih, const float* __restrict__ bhh,
                            const float* __restrict__ Wout)
{
    int idx = blockIdx.x * blockDim.x + threadIdx.x;    // over 1024*256
    if (idx < 4*HH*HH) {
        int j = idx / HH;      // gate row 0..1023
        int k = idx % HH;
        int g = j >> 8, c = j & 255;
        float w, w0;
        if (g == 0)      { float a = Wih[c*HH+k],       b = Whh[c*HH+k];       w = a + b; w0 = b; }
        else if (g == 1) { float a = Wih[(256+c)*HH+k], b = Whh[(256+c)*HH+k]; w = a + b; w0 = b; }
        else if (g == 2) { w = Wih[(512+c)*HH+k]; w0 = 0.f; }
        else             { w = Whh[(512+c)*HH+k]; w0 = w;  }
        __half hi = __float2half_rn(w);
        g_Whi[idx] = hi;
        g_Wlo[idx] = __float2half_rn(w - __half2float(hi));
        __half hi0 = __float2half_rn(w0);
        g_Whi0[idx] = hi0;
        g_Wlo0[idx] = __float2half_rn(w0 - __half2float(hi0));
    }
    if (idx < 32*HH) {
        int o = idx >> 8, k = idx & 255;
        g_WoutH[idx] = __float2half_rn(o < OUT_ ? Wout[o*HH + k] : 0.f);
    }
    if (idx < 4*HH) {
        int g = idx >> 8, c = idx & 255;
        float b;
        if (g == 0)      b = bih[c]     + bhh[c];
        else if (g == 1) b = bih[256+c] + bhh[256+c];
        else if (g == 2) b = bih[512+c];
        else             b = bhh[512+c];
        g_b4[idx] = b;
    }
}

// split h0 (fp32) into fp16
__global__ void split_kernel(const float* __restrict__ h, __half* __restrict__ o)
{
    int idx = blockIdx.x * blockDim.x + threadIdx.x;
    if (idx < BB*HH) o[idx] = __float2half_rn(h[idx]);
}

// ---------------- main GRU step: fp16 2-term split GEMM + fused epilogue ----------------
// grid = (BB/128, HH/64) = (128, 4); 512 threads = 16 warps, warp tile 64x32 (2M x 8N grid)
__global__ void __launch_bounds__(512, 1)
gru_mma_kernel(const __half* __restrict__ Ah,
               const __half* __restrict__ Whi, const __half* __restrict__ Wlo,
               const float* __restrict__ hprev, float* __restrict__ hout,
               __half* __restrict__ Oh)
{
    extern __shared__ __align__(16) char dsm[];
    const uint32_t sb = smem_u32(dsm);

    const int tid  = threadIdx.x;
    const int lane = tid & 31;
    const int warp = tid >> 5;
    const int wm   = warp >> 3;        // 0..1  -> m offset wm*64
    const int wn   = warp & 7;         // 0..7  -> n offset wn*32
    const int row0 = blockIdx.x * 128;
    const int col0 = blockIdx.y * 64;

    const int aRow  = wm*64 + (lane & 15);
    const int aKoff = (lane >> 4) * 8;
    const int bRow  = wn*32 + (lane >> 4) * 8 + (lane & 7);
    const int bKoff = ((lane >> 3) & 1) * 8;

    const int ar  = tid >> 2, aseg = tid & 3;         // A: 512 x 16B chunks

    float acc[4][4][4];
#pragma unroll
    for (int mt = 0; mt < 4; mt++)
#pragma unroll
        for (int nt = 0; nt < 4; nt++)
#pragma unroll
            for (int q = 0; q < 4; q++) acc[mt][nt][q] = 0.f;

    auto load_stage = [&](int s, uint32_t bufoff) {
        const int kb = s * 32;
        {
            uint32_t d = sb + bufoff + A_OFF + (uint32_t)(ar*ST + aseg*8) * 2;
            size_t go = (size_t)(row0 + ar) * HH + kb + aseg*8;
            cpa16(d, Ah + go);
        }
#pragma unroll
        for (int i = 0; i < 2; i++) {
            int e = tid + i * 512;
            int n = e >> 2, seg = e & 3;
            int j = ((n >> 6) << 8) + col0 + (n & 63);   // global gate row
            uint32_t d = sb + bufoff + (uint32_t)(n*ST + seg*8) * 2;
            size_t go = (size_t)j * HH + kb + seg*8;
            cpa16(d + BHI_OFF, Whi + go);
            cpa16(d + BLO_OFF, Wlo + go);
        }
    };

    load_stage(0, 0);
    asm volatile("cp.async.commit_group;" ::: "memory");

    for (int s = 0; s < 8; s++) {
        asm volatile("cp.async.wait_group 0;" ::: "memory");
        __syncthreads();
        if (s < 7) {
            load_stage(s + 1, ((s + 1) & 1) * BUFB);
            asm volatile("cp.async.commit_group;" ::: "memory");
        }
        const uint32_t base = sb + (s & 1) * BUFB;

#pragma unroll
        for (int kc = 0; kc < 2; kc++) {
            uint32_t bh[8], bl[8];
#pragma unroll
            for (int p = 0; p < 2; p++) {
                uint32_t baddr = base + BHI_OFF +
                    (uint32_t)((bRow + p*16)*ST + kc*16 + bKoff) * 2;
                ldm4(&bh[p*4], baddr);
                ldm4(&bl[p*4], baddr + (BLO_OFF - BHI_OFF));
            }
#pragma unroll
            for (int mt = 0; mt < 4; mt++) {
                uint32_t aaddr = base + A_OFF +
                    (uint32_t)((aRow + mt*16)*ST + kc*16 + aKoff) * 2;
                uint32_t ah[4];
                ldm4(ah, aaddr);
#pragma unroll
                for (int nt = 0; nt < 4; nt++) {
                    mma16816(acc[mt][nt], ah, &bh[nt*2]);   // A * Whi
                    mma16816(acc[mt][nt], ah, &bl[nt*2]);   // A * Wlo
                }
            }
        }
    }

    // ---- epilogue: acc -> smem [128][260] fp32, then gates + h update ----
    __syncthreads();
    float* S = (float*)dsm;
#pragma unroll
    for (int mt = 0; mt < 4; mt++) {
        int rb = wm*64 + mt*16 + (lane >> 2);
#pragma unroll
        for (int nt = 0; nt < 4; nt++) {
            int cb = wn*32 + nt*8 + (lane & 3)*2;
            *(float2*)&S[rb*260 + cb]       = make_float2(acc[mt][nt][0], acc[mt][nt][1]);
            *(float2*)&S[(rb+8)*260 + cb]   = make_float2(acc[mt][nt][2], acc[mt][nt][3]);
        }
    }
    __syncthreads();

#pragma unroll
    for (int i = 0; i < 4; i++) {
        int e  = tid + i * 512;        // 128 rows x 16 col-chunks
        int r  = e >> 4;
        int cl = (e & 15) * 4;
        int cg = col0 + cl;
        const float* Sr = &S[r*260];
        float4 vr = *(const float4*)&Sr[cl];
        float4 vz = *(const float4*)&Sr[64 + cl];
        float4 vn = *(const float4*)&Sr[128 + cl];
        float4 vh = *(const float4*)&Sr[192 + cl];
        float ga[4] = {vr.x, vr.y, vr.z, vr.w};
        float gz[4] = {vz.x, vz.y, vz.z, vz.w};
        float gn[4] = {vn.x, vn.y, vn.z, vn.w};
        float gh[4] = {vh.x, vh.y, vh.z, vh.w};

        float4 hp4 = *(const float4*)(hprev + (size_t)(row0 + r)*HH + cg);
        float hp[4] = {hp4.x, hp4.y, hp4.z, hp4.w};

        float hn[4];
#pragma unroll
        for (int j = 0; j < 4; j++) {
            int c = cg + j;
            float arv = ga[j] + g_b4[c];
            float azv = gz[j] + g_b4[256 + c];
            float anv = gn[j] + g_b4[512 + c];
            float ahv = gh[j] + g_b4[768 + c];
            float rg = 1.f / (1.f + __expf(-arv));
            float zg = 1.f / (1.f + __expf(-azv));
            float x  = anv + rg * ahv;
            float t  = __expf(-2.f * fabsf(x));
            float th = (1.f - t) / (1.f + t);
            th = copysignf(th, x);
            hn[j] = (1.f - zg) * th + zg * hp[j];
        }
        *(float4*)(hout + (size_t)(row0 + r)*HH + cg) = make_float4(hn[0], hn[1], hn[2], hn[3]);

        union { uint2 u; __half h[4]; } ph;
#pragma unroll
        for (int j = 0; j < 4; j++) ph.h[j] = __float2half_rn(hn[j]);
        *(uint2*)(Oh + (size_t)(row0 + r)*HH + cg) = ph.u;
    }
}

// ---------------- out_proj: fp16 HMMA GEMM, M=64/CTA, N=32 (31+pad), K=256 ----------------
// block = 128 (4 warps), each warp: 16 rows x 32 cols; grid = BB/64 = 256
__global__ void __launch_bounds__(128)
out_proj_kernel(const __half* __restrict__ Ah, const float* __restrict__ bout,
                float* __restrict__ y, int step)
{
    extern __shared__ __align__(16) char dsm[];
    const uint32_t sb = smem_u32(dsm);

    const int tid  = threadIdx.x;
    const int lane = tid & 31;
    const int warp = tid >> 5;
    const int row0 = blockIdx.x * 64;

    // load A: 64 rows x 256 halves = 2048 x 16B chunks, 16/thread
#pragma unroll
    for (int i = 0; i < 16; i++) {
        int e = tid + i * 128;
        int r = e >> 5, seg = e & 31;
        cpa16(sb + OPA_OFF + (uint32_t)(r*OP_ST + seg*8)*2,
              Ah + (size_t)(row0 + r)*HH + seg*8);
    }
    // load W: 32 rows x 256 halves = 1024 chunks, 8/thread
#pragma unroll
    for (int i = 0; i < 8; i++) {
        int e = tid + i * 128;
        int r = e >> 5, seg = e & 31;
        cpa16(sb + OPW_OFF + (uint32_t)(r*OP_ST + seg*8)*2,
              g_WoutH + (size_t)r*HH + seg*8);
    }
    asm volatile("cp.async.commit_group;" ::: "memory");
    asm volatile("cp.async.wait_group 0;" ::: "memory");
    __syncthreads();

    const int aRow  = warp*16 + (lane & 15);
    const int aKoff = (lane >> 4) * 8;
    const int bRow  = (lane >> 4) * 8 + (lane & 7);
    const int bKoff = ((lane >> 3) & 1) * 8;

    float acc[4][4];
#pragma unroll
    for (int nt = 0; nt < 4; nt++)
#pragma unroll
        for (int q = 0; q < 4; q++) acc[nt][q] = 0.f;

#pragma unroll
    for (int ks = 0; ks < 16; ks++) {
        uint32_t ah[4], bh[8];
        ldm4(ah, sb + OPA_OFF + (uint32_t)(aRow*OP_ST + ks*16 + aKoff)*2);
#pragma unroll
        for (int p = 0; p < 2; p++)
            ldm4(&bh[p*4], sb + OPW_OFF + (uint32_t)((bRow + p*16)*OP_ST + ks*16 + bKoff)*2);
#pragma unroll
        for (int nt = 0; nt < 4; nt++)
            mma16816(acc[nt], ah, &bh[nt*2]);
    }

    // store: rows warp*16 + lane>>2 (+8), cols nt*8 + (lane&3)*2 (+1)
    const int rl  = warp*16 + (lane >> 2);
    const int cb  = (lane & 3) * 2;
#pragma unroll
    for (int nt = 0; nt < 4; nt++) {
        int col = nt*8 + cb;                     // even, 0..30
        float b0 = bout[col];
        size_t base0 = (size_t)(row0 + rl) * YSTRIDE + (size_t)step * OUT_;
        size_t base1 = base0 + 8u * YSTRIDE;
        y[base0 + col] = acc[nt][0] + b0;
        y[base1 + col] = acc[nt][2] + b0;
        if (col < 30) {
            float b1 = bout[col + 1];
            y[base0 + col + 1] = acc[nt][1] + b1;
            y[base1 + col + 1] = acc[nt][3] + b1;
        }
    }
}

// ---------------- host ----------------
extern "C" void kernel_launch(void* const* d_in, const int* in_sizes, int n_in,
                              void* d_out, int out_size)
{
    const float* hidden = (const float*)d_in[0];
    const float* Wih    = (const float*)d_in[1];
    const float* Whh    = (const float*)d_in[2];
    const float* bih    = (const float*)d_in[3];
    const float* bhh    = (const float*)d_in[4];
    const float* Wout   = (const float*)d_in[5];
    const float* bout   = (const float*)d_in[6];
    float* y = (float*)d_out;

    __half *pWhi, *pWlo, *pWhi0, *pWlo0, *ps0, *ps1;
    float *phA, *phB;
    cudaGetSymbolAddress((void**)&pWhi,  g_Whi);
    cudaGetSymbolAddress((void**)&pWlo,  g_Wlo);
    cudaGetSymbolAddress((void**)&pWhi0, g_Whi0);
    cudaGetSymbolAddress((void**)&pWlo0, g_Wlo0);
    cudaGetSymbolAddress((void**)&ps0,   g_s0);
    cudaGetSymbolAddress((void**)&ps1,   g_s1);
    cudaGetSymbolAddress((void**)&phA,   g_hA);
    cudaGetSymbolAddress((void**)&phB,   g_hB);

    cudaFuncSetAttribute(gru_mma_kernel, cudaFuncAttributeMaxDynamicSharedMemorySize, SMEM_ALLOC);
    cudaFuncSetAttribute(out_proj_kernel, cudaFuncAttributeMaxDynamicSharedMemorySize, OP_SMEM);

    prep_kernel<<<(4*HH*HH + 255)/256, 256>>>(Wih, Whh, bih, bhh, Wout);
    split_kernel<<<(BB*HH + 255)/256, 256>>>(hidden, ps0);

    dim3 grid(BB/128, HH/64);   // (128, 4)

    // step 0: x = 0 variant weights, h_prev = harness input; h_0 -> phA (fp32), ps1 (fp16)
    gru_mma_kernel<<<grid, 512, SMEM_ALLOC>>>(ps0, pWhi0, pWlo0, hidden, phA, ps1);
    out_proj_kernel<<<BB/64, 128, OP_SMEM>>>(ps1, bout, y, 0);

    float* hin = phA;  float* hot = phB;
    __half *ih = ps1, *oh = ps0;

    for (int t = 1; t < STEPS; t++) {
        gru_mma_kernel<<<grid, 512, SMEM_ALLOC>>>(ih, pWhi, pWlo, hin, hot, oh);
        out_proj_kernel<<<BB/64, 128, OP_SMEM>>>(oh, bout, y, t);
        float* tf = hin; hin = hot; hot = tf;
        __half* th = ih; ih = oh; oh = th;
    }
}

// round 10
// speedup vs baseline: 3.1137x; 1.0601x over previous
#include <cuda_runtime.h>
#include <cuda_fp16.h>
#include <math.h>
#include <stdint.h>

#define BB 16384
#define HH 256
#define STEPS 120
#define OUT_ 31
#define YSTRIDE (STEPS*OUT_)

// ---- gru GEMM tiling: CTA = 128 rows x 256 gate cols (4 gates x 64 hidden cols) ----
#define ST   40            // smem row stride in halves (32 data + 8 pad)
#define A_OFF   0u
#define BHI_OFF 10240u     // A stage = 128*40*2 = 10240 B
#define BLO_OFF 30720u     // Bhi = 256*40*2 = 20480 B
#define BUFB    51200u     // stage total
#define SMEM_ALLOC 102400  // 2 stages, no epilogue buffer needed

// ---- out_proj tiling: M=32/CTA, N=32, K=256 ----
#define OP_ST 264          // halves per smem row (256 + 8 pad)
#define OPA_OFF 0u
#define OPW_OFF 16896u     // A = 32*264*2
#define OP_SMEM 33792u

// ---------------- device scratch (no allocs allowed) ----------------
__device__ __half g_Whi [4*HH*HH];   // combined gate weights [1024 rows][256 K], steps>=1
__device__ __half g_Wlo [4*HH*HH];
__device__ __half g_Whi0[4*HH*HH];   // step-0 variant (x=0)
__device__ __half g_Wlo0[4*HH*HH];
__device__ __half g_WoutH[32*HH];    // fp16 Wout, row 31 zero-padded
__device__ float g_b4[4*HH];         // fused biases [g*256+c]
__device__ float g_hA[BB*HH];
__device__ float g_hB[BB*HH];
__device__ __half g_s0[BB*HH], g_s1[BB*HH];   // fp16 h state ping-pong

// ---------------- PTX helpers (family-safe: sm_80-era only) ----------------
__device__ __forceinline__ uint32_t smem_u32(const void* p) {
    uint32_t a;
    asm("{ .reg .u64 t; cvta.to.shared.u64 t, %1; cvt.u32.u64 %0, t; }" : "=r"(a) : "l"(p));
    return a;
}
__device__ __forceinline__ void cpa16(uint32_t dst, const void* src) {
    asm volatile("cp.async.cg.shared.global [%0], [%1], 16;" :: "r"(dst), "l"(src) : "memory");
}
__device__ __forceinline__ void ldm4(uint32_t* r, uint32_t addr) {
    asm volatile("ldmatrix.sync.aligned.m8n8.x4.shared.b16 {%0,%1,%2,%3}, [%4];"
                 : "=r"(r[0]), "=r"(r[1]), "=r"(r[2]), "=r"(r[3]) : "r"(addr));
}
__device__ __forceinline__ void mma16816(float* c, const uint32_t* a, const uint32_t* b) {
    asm volatile("mma.sync.aligned.m16n8k16.row.col.f32.f16.f16.f32 "
                 "{%0,%1,%2,%3}, {%4,%5,%6,%7}, {%8,%9}, {%0,%1,%2,%3};"
                 : "+f"(c[0]), "+f"(c[1]), "+f"(c[2]), "+f"(c[3])
                 : "r"(a[0]), "r"(a[1]), "r"(a[2]), "r"(a[3]), "r"(b[0]), "r"(b[1]));
}

// ---------------- prep: combined weights, fp16 split; Wout fp16 ----------------
__global__ void prep_kernel(const float* __restrict__ Wih, const float* __restrict__ Whh,
                            const float* __restrict__ bih, const float* __restrict__ bhh,
                            const float* __restrict__ Wout)
{
    int idx = blockIdx.x * blockDim.x + threadIdx.x;    // over 1024*256
    if (idx < 4*HH*HH) {
        int j = idx / HH;      // gate row 0..1023
        int k = idx % HH;
        int g = j >> 8, c = j & 255;
        float w, w0;
        if (g == 0)      { float a = Wih[c*HH+k],       b = Whh[c*HH+k];       w = a + b; w0 = b; }
        else if (g == 1) { float a = Wih[(256+c)*HH+k], b = Whh[(256+c)*HH+k]; w = a + b; w0 = b; }
        else if (g == 2) { w = Wih[(512+c)*HH+k]; w0 = 0.f; }
        else             { w = Whh[(512+c)*HH+k]; w0 = w;  }
        __half hi = __float2half_rn(w);
        g_Whi[idx] = hi;
        g_Wlo[idx] = __float2half_rn(w - __half2float(hi));
        __half hi0 = __float2half_rn(w0);
        g_Whi0[idx] = hi0;
        g_Wlo0[idx] = __float2half_rn(w0 - __half2float(hi0));
    }
    if (idx < 32*HH) {
        int o = idx >> 8, k = idx & 255;
        g_WoutH[idx] = __float2half_rn(o < OUT_ ? Wout[o*HH + k] : 0.f);
    }
    if (idx < 4*HH) {
        int g = idx >> 8, c = idx & 255;
        float b;
        if (g == 0)      b = bih[c]     + bhh[c];
        else if (g == 1) b = bih[256+c] + bhh[256+c];
        else if (g == 2) b = bih[512+c];
        else             b = bhh[512+c];
        g_b4[idx] = b;
    }
}

// split h0 (fp32) into fp16
__global__ void split_kernel(const float* __restrict__ h, __half* __restrict__ o)
{
    int idx = blockIdx.x * blockDim.x + threadIdx.x;
    if (idx < BB*HH) o[idx] = __float2half_rn(h[idx]);
}

// ---------------- main GRU step: fp16 2-term split GEMM, gate-interleaved warps ----------------
// grid = (BB/128, HH/64) = (128, 4); 512 threads = 16 warps.
// warp (wm, wn): rows wm*64..+64, hidden cols wn*8..+8 across ALL 4 gates
// (n-tiles at gate offsets g*64) -> per-thread in-register gate epilogue.
__global__ void __launch_bounds__(512, 1)
gru_mma_kernel(const __half* __restrict__ Ah,
               const __half* __restrict__ Whi, const __half* __restrict__ Wlo,
               const float* __restrict__ hprev, float* __restrict__ hout,
               __half* __restrict__ Oh)
{
    extern __shared__ __align__(16) char dsm[];
    const uint32_t sb = smem_u32(dsm);

    const int tid  = threadIdx.x;
    const int lane = tid & 31;
    const int warp = tid >> 5;
    const int wm   = warp >> 3;        // 0..1  -> m offset wm*64
    const int wn   = warp & 7;         // 0..7  -> hidden col chunk wn*8
    const int row0 = blockIdx.x * 128;
    const int col0 = blockIdx.y * 64;

    // A-frag addressing (standard 16x16 ldm4)
    const int aRow  = wm*64 + (lane & 15);
    const int aKoff = (lane >> 4) * 8;

    // B-frag addressing: ldm4 loads 4 disjoint 8x8 tiles, one per lane-group.
    // lane-group lg = lane>>3: gate = lg>>1 (+2 for 2nd ldm4), k-half = lg&1
    const int lg = lane >> 3, lr = lane & 7;
    const int bRowOff = (((lg >> 1) * 64) + wn*8 + lr) * ST + (lg & 1) * 8;

    const int ar = tid >> 2, aseg = tid & 3;       // A stage loads: 512 x 16B chunks

    float acc[4][4][4];   // [mt][gate][q]
#pragma unroll
    for (int mt = 0; mt < 4; mt++)
#pragma unroll
        for (int g = 0; g < 4; g++)
#pragma unroll
            for (int q = 0; q < 4; q++) acc[mt][g][q] = 0.f;

    auto load_stage = [&](int s, uint32_t bufoff) {
        const int kb = s * 32;
        {
            uint32_t d = sb + bufoff + A_OFF + (uint32_t)(ar*ST + aseg*8) * 2;
            size_t go = (size_t)(row0 + ar) * HH + kb + aseg*8;
            cpa16(d, Ah + go);
        }
#pragma unroll
        for (int i = 0; i < 2; i++) {
            int e = tid + i * 512;
            int n = e >> 2, seg = e & 3;
            int j = ((n >> 6) << 8) + col0 + (n & 63);   // global gate row
            uint32_t d = sb + bufoff + (uint32_t)(n*ST + seg*8) * 2;
            size_t go = (size_t)j * HH + kb + seg*8;
            cpa16(d + BHI_OFF, Whi + go);
            cpa16(d + BLO_OFF, Wlo + go);
        }
    };

    load_stage(0, 0);
    asm volatile("cp.async.commit_group;" ::: "memory");

    for (int s = 0; s < 8; s++) {
        asm volatile("cp.async.wait_group 0;" ::: "memory");
        __syncthreads();
        if (s < 7) {
            load_stage(s + 1, ((s + 1) & 1) * BUFB);
            asm volatile("cp.async.commit_group;" ::: "memory");
        }
        const uint32_t base = sb + (s & 1) * BUFB;

#pragma unroll
        for (int kc = 0; kc < 2; kc++) {
            uint32_t bh[8], bl[8];
            {
                uint32_t a0 = base + BHI_OFF + (uint32_t)(bRowOff + kc*16) * 2;
                uint32_t a1 = a0 + (uint32_t)(128*ST) * 2;   // gates 2,3
                ldm4(&bh[0], a0);
                ldm4(&bh[4], a1);
                ldm4(&bl[0], a0 + (BLO_OFF - BHI_OFF));
                ldm4(&bl[4], a1 + (BLO_OFF - BHI_OFF));
            }
#pragma unroll
            for (int mt = 0; mt < 4; mt++) {
                uint32_t aaddr = base + A_OFF +
                    (uint32_t)((aRow + mt*16)*ST + kc*16 + aKoff) * 2;
                uint32_t ah[4];
                ldm4(ah, aaddr);
#pragma unroll
                for (int g = 0; g < 4; g++) {
                    mma16816(acc[mt][g], ah, &bh[g*2]);   // A * Whi
                    mma16816(acc[mt][g], ah, &bl[g*2]);   // A * Wlo
                }
            }
        }
    }

    // ---- in-register epilogue: this thread owns cols (cg, cg+1) for all gates ----
    const int cA = wn*8 + (lane & 3)*2;     // local hidden col
    const int cg = col0 + cA;
    const float2 br = *(const float2*)&g_b4[cg];
    const float2 bz = *(const float2*)&g_b4[256 + cg];
    const float2 bn = *(const float2*)&g_b4[512 + cg];
    const float2 bm = *(const float2*)&g_b4[768 + cg];
    const float bias[4][2] = {{br.x,br.y},{bz.x,bz.y},{bn.x,bn.y},{bm.x,bm.y}};

#pragma unroll
    for (int mt = 0; mt < 4; mt++) {
        const int rr = row0 + wm*64 + mt*16 + (lane >> 2);
#pragma unroll
        for (int p = 0; p < 2; p++) {
            const int r = rr + p*8;
            float2 hp = *(const float2*)(hprev + (size_t)r*HH + cg);
            float hpv[2] = {hp.x, hp.y};
            float hn[2];
#pragma unroll
            for (int j = 0; j < 2; j++) {
                int q = p*2 + j;
                float arv = acc[mt][0][q] + bias[0][j];
                float azv = acc[mt][1][q] + bias[1][j];
                float anv = acc[mt][2][q] + bias[2][j];
                float ahv = acc[mt][3][q] + bias[3][j];
                float rg = 1.f / (1.f + __expf(-arv));
                float zg = 1.f / (1.f + __expf(-azv));
                float x  = anv + rg * ahv;
                float t  = __expf(-2.f * fabsf(x));
                float th = (1.f - t) / (1.f + t);
                th = copysignf(th, x);
                hn[j] = (1.f - zg) * th + zg * hpv[j];
            }
            *(float2*)(hout + (size_t)r*HH + cg) = make_float2(hn[0], hn[1]);
            __half2 h2 = __floats2half2_rn(hn[0], hn[1]);
            *(__half2*)(Oh + (size_t)r*HH + cg) = h2;
        }
    }
}

// ---------------- out_proj: fp16 HMMA GEMM, M=32/CTA, N=32 (31+pad), K=256 ----------------
// block = 64 (2 warps), each warp: 16 rows x 32 cols; grid = BB/32 = 512
__global__ void __launch_bounds__(64)
out_proj_kernel(const __half* __restrict__ Ah, const float* __restrict__ bout,
                float* __restrict__ y, int step)
{
    extern __shared__ __align__(16) char dsm[];
    const uint32_t sb = smem_u32(dsm);

    const int tid  = threadIdx.x;
    const int lane = tid & 31;
    const int warp = tid >> 5;
    const int row0 = blockIdx.x * 32;

    // load A: 32 rows x 256 halves = 1024 x 16B chunks, 16/thread
#pragma unroll
    for (int i = 0; i < 16; i++) {
        int e = tid + i * 64;
        int r = e >> 5, seg = e & 31;
        cpa16(sb + OPA_OFF + (uint32_t)(r*OP_ST + seg*8)*2,
              Ah + (size_t)(row0 + r)*HH + seg*8);
    }
    // load W: 32 rows x 256 halves = 1024 chunks, 16/thread
#pragma unroll
    for (int i = 0; i < 16; i++) {
        int e = tid + i * 64;
        int r = e >> 5, seg = e & 31;
        cpa16(sb + OPW_OFF + (uint32_t)(r*OP_ST + seg*8)*2,
              g_WoutH + (size_t)r*HH + seg*8);
    }
    asm volatile("cp.async.commit_group;" ::: "memory");
    asm volatile("cp.async.wait_group 0;" ::: "memory");
    __syncthreads();

    const int aRow  = warp*16 + (lane & 15);
    const int aKoff = (lane >> 4) * 8;
    const int bRow  = (lane >> 4) * 8 + (lane & 7);
    const int bKoff = ((lane >> 3) & 1) * 8;

    float acc[4][4];
#pragma unroll
    for (int nt = 0; nt < 4; nt++)
#pragma unroll
        for (int q = 0; q < 4; q++) acc[nt][q] = 0.f;

#pragma unroll
    for (int ks = 0; ks < 16; ks++) {
        uint32_t ah[4], bh[8];
        ldm4(ah, sb + OPA_OFF + (uint32_t)(aRow*OP_ST + ks*16 + aKoff)*2);
#pragma unroll
        for (int p = 0; p < 2; p++)
            ldm4(&bh[p*4], sb + OPW_OFF + (uint32_t)((bRow + p*16)*OP_ST + ks*16 + bKoff)*2);
#pragma unroll
        for (int nt = 0; nt < 4; nt++)
            mma16816(acc[nt], ah, &bh[nt*2]);
    }

    const int rl  = warp*16 + (lane >> 2);
    const int cb  = (lane & 3) * 2;
#pragma unroll
    for (int nt = 0; nt < 4; nt++) {
        int col = nt*8 + cb;                     // even, 0..30
        float b0 = bout[col];
        size_t base0 = (size_t)(row0 + rl) * YSTRIDE + (size_t)step * OUT_;
        size_t base1 = base0 + 8u * YSTRIDE;
        y[base0 + col] = acc[nt][0] + b0;
        y[base1 + col] = acc[nt][2] + b0;
        if (col < 30) {
            float b1 = bout[col + 1];
            y[base0 + col + 1] = acc[nt][1] + b1;
            y[base1 + col + 1] = acc[nt][3] + b1;
        }
    }
}

// ---------------- host ----------------
extern "C" void kernel_launch(void* const* d_in, const int* in_sizes, int n_in,
                              void* d_out, int out_size)
{
    const float* hidden = (const float*)d_in[0];
    const float* Wih    = (const float*)d_in[1];
    const float* Whh    = (const float*)d_in[2];
    const float* bih    = (const float*)d_in[3];
    const float* bhh    = (const float*)d_in[4];
    const float* Wout   = (const float*)d_in[5];
    const float* bout   = (const float*)d_in[6];
    float* y = (float*)d_out;

    __half *pWhi, *pWlo, *pWhi0, *pWlo0, *ps0, *ps1;
    float *phA, *phB;
    cudaGetSymbolAddress((void**)&pWhi,  g_Whi);
    cudaGetSymbolAddress((void**)&pWlo,  g_Wlo);
    cudaGetSymbolAddress((void**)&pWhi0, g_Whi0);
    cudaGetSymbolAddress((void**)&pWlo0, g_Wlo0);
    cudaGetSymbolAddress((void**)&ps0,   g_s0);
    cudaGetSymbolAddress((void**)&ps1,   g_s1);
    cudaGetSymbolAddress((void**)&phA,   g_hA);
    cudaGetSymbolAddress((void**)&phB,   g_hB);

    cudaFuncSetAttribute(gru_mma_kernel, cudaFuncAttributeMaxDynamicSharedMemorySize, SMEM_ALLOC);
    cudaFuncSetAttribute(out_proj_kernel, cudaFuncAttributeMaxDynamicSharedMemorySize, OP_SMEM);

    prep_kernel<<<(4*HH*HH + 255)/256, 256>>>(Wih, Whh, bih, bhh, Wout);
    split_kernel<<<(BB*HH + 255)/256, 256>>>(hidden, ps0);

    dim3 grid(BB/128, HH/64);   // (128, 4)

    // step 0: x = 0 variant weights, h_prev = harness input; h_0 -> phA (fp32), ps1 (fp16)
    gru_mma_kernel<<<grid, 512, SMEM_ALLOC>>>(ps0, pWhi0, pWlo0, hidden, phA, ps1);
    out_proj_kernel<<<BB/32, 64, OP_SMEM>>>(ps1, bout, y, 0);

    float* hin = phA;  float* hot = phB;
    __half *ih = ps1, *oh = ps0;

    for (int t = 1; t < STEPS; t++) {
        gru_mma_kernel<<<grid, 512, SMEM_ALLOC>>>(ih, pWhi, pWlo, hin, hot, oh);
        out_proj_kernel<<<BB/32, 64, OP_SMEM>>>(oh, bout, y, t);
        float* tf = hin; hin = hot; hot = tf;
        __half* th = ih; ih = oh; oh = th;
    }
}

// round 11
// speedup vs baseline: 3.3390x; 1.0724x over previous
#include <cuda_runtime.h>
#include <cuda_fp16.h>
#include <math.h>
#include <stdint.h>

#define BB 16384
#define HH 256
#define STEPS 120
#define OUT_ 31
#define YSTRIDE (STEPS*OUT_)

// ---- gru GEMM tiling: CTA = 128 rows x 256 gate cols (4 gates x 64 hidden cols) ----
#define ST   40            // smem row stride in halves (32 data + 8 pad)
#define A_OFF   0u
#define BHI_OFF 10240u     // A stage = 128*40*2 = 10240 B
#define BLO_OFF 30720u     // Bhi = 256*40*2 = 20480 B
#define BUFB    51200u     // stage total
#define SMEM_ALLOC 102400  // 2 stages

// ---- fused y-projection (blockIdx.y==4): M=128, N=32, K=256 ----
#define OP_ST 264          // halves per smem row (256 + 8 pad)
#define FYA_OFF 0u
#define FYW_OFF 67584u     // A = 128*264*2; + W 32*264*2 = 16896 -> 84480 <= SMEM_ALLOC

// ---- standalone final out_proj: M=64/CTA ----
#define OPA_OFF 0u
#define OPW_OFF 33792u     // A = 64*264*2
#define OP_SMEM 50688u

// ---------------- device scratch (no allocs allowed) ----------------
__device__ __half g_Whi [4*HH*HH];
__device__ __half g_Wlo [4*HH*HH];
__device__ __half g_Whi0[4*HH*HH];
__device__ __half g_Wlo0[4*HH*HH];
__device__ __half g_WoutH[32*HH];    // fp16 Wout, row 31 zero-padded
__device__ float g_b4[4*HH];
__device__ float g_hA[BB*HH];
__device__ float g_hB[BB*HH];
__device__ __half g_s0[BB*HH], g_s1[BB*HH];

// ---------------- PTX helpers (family-safe: sm_80-era only) ----------------
__device__ __forceinline__ uint32_t smem_u32(const void* p) {
    uint32_t a;
    asm("{ .reg .u64 t; cvta.to.shared.u64 t, %1; cvt.u32.u64 %0, t; }" : "=r"(a) : "l"(p));
    return a;
}
__device__ __forceinline__ void cpa16(uint32_t dst, const void* src) {
    asm volatile("cp.async.cg.shared.global [%0], [%1], 16;" :: "r"(dst), "l"(src) : "memory");
}
__device__ __forceinline__ void ldm4(uint32_t* r, uint32_t addr) {
    asm volatile("ldmatrix.sync.aligned.m8n8.x4.shared.b16 {%0,%1,%2,%3}, [%4];"
                 : "=r"(r[0]), "=r"(r[1]), "=r"(r[2]), "=r"(r[3]) : "r"(addr));
}
__device__ __forceinline__ void mma16816(float* c, const uint32_t* a, const uint32_t* b) {
    asm volatile("mma.sync.aligned.m16n8k16.row.col.f32.f16.f16.f32 "
                 "{%0,%1,%2,%3}, {%4,%5,%6,%7}, {%8,%9}, {%0,%1,%2,%3};"
                 : "+f"(c[0]), "+f"(c[1]), "+f"(c[2]), "+f"(c[3])
                 : "r"(a[0]), "r"(a[1]), "r"(a[2]), "r"(a[3]), "r"(b[0]), "r"(b[1]));
}

// ---------------- prep ----------------
__global__ void prep_kernel(const float* __restrict__ Wih, const float* __restrict__ Whh,
                            const float* __restrict__ bih, const float* __restrict__ bhh,
                            const float* __restrict__ Wout)
{
    int idx = blockIdx.x * blockDim.x + threadIdx.x;
    if (idx < 4*HH*HH) {
        int j = idx / HH;
        int k = idx % HH;
        int g = j >> 8, c = j & 255;
        float w, w0;
        if (g == 0)      { float a = Wih[c*HH+k],       b = Whh[c*HH+k];       w = a + b; w0 = b; }
        else if (g == 1) { float a = Wih[(256+c)*HH+k], b = Whh[(256+c)*HH+k]; w = a + b; w0 = b; }
        else if (g == 2) { w = Wih[(512+c)*HH+k]; w0 = 0.f; }
        else             { w = Whh[(512+c)*HH+k]; w0 = w;  }
        __half hi = __float2half_rn(w);
        g_Whi[idx] = hi;
        g_Wlo[idx] = __float2half_rn(w - __half2float(hi));
        __half hi0 = __float2half_rn(w0);
        g_Whi0[idx] = hi0;
        g_Wlo0[idx] = __float2half_rn(w0 - __half2float(hi0));
    }
    if (idx < 32*HH) {
        int o = idx >> 8, k = idx & 255;
        g_WoutH[idx] = __float2half_rn(o < OUT_ ? Wout[o*HH + k] : 0.f);
    }
    if (idx < 4*HH) {
        int g = idx >> 8, c = idx & 255;
        float b;
        if (g == 0)      b = bih[c]     + bhh[c];
        else if (g == 1) b = bih[256+c] + bhh[256+c];
        else if (g == 2) b = bih[512+c];
        else             b = bhh[512+c];
        g_b4[idx] = b;
    }
}

__global__ void split_kernel(const float* __restrict__ h, __half* __restrict__ o)
{
    int idx = blockIdx.x * blockDim.x + threadIdx.x;
    if (idx < BB*HH) o[idx] = __float2half_rn(h[idx]);
}

// ---------------- fused GRU step + previous-step y projection ----------------
// grid = (128, 5), 512 threads.
//   blockIdx.y < 4 : gru GEMM (rows bx*128, hidden cols by*64), gate-interleaved warps
//   blockIdx.y == 4: y_{step-1} = Ah @ Wout^T + bout (skipped when step==0)
__global__ void __launch_bounds__(512, 1)
gru_mma_kernel(const __half* __restrict__ Ah,
               const __half* __restrict__ Whi, const __half* __restrict__ Wlo,
               const float* __restrict__ hprev, float* __restrict__ hout,
               __half* __restrict__ Oh,
               const float* __restrict__ bout, float* __restrict__ y, int step)
{
    extern __shared__ __align__(16) char dsm[];
    const uint32_t sb = smem_u32(dsm);

    const int tid  = threadIdx.x;
    const int lane = tid & 31;
    const int warp = tid >> 5;
    const int row0 = blockIdx.x * 128;

    if (blockIdx.y == 4) {
        // ---------- y-projection block ----------
        if (step == 0) return;
        // load A: 128 rows x 256 halves = 4096 x 16B chunks, 8/thread
#pragma unroll
        for (int i = 0; i < 8; i++) {
            int e = tid + i * 512;
            int r = e >> 5, seg = e & 31;
            cpa16(sb + FYA_OFF + (uint32_t)(r*OP_ST + seg*8)*2,
                  Ah + (size_t)(row0 + r)*HH + seg*8);
        }
        // load W: 32 rows x 256 halves = 1024 chunks, 2/thread
#pragma unroll
        for (int i = 0; i < 2; i++) {
            int e = tid + i * 512;
            int r = e >> 5, seg = e & 31;
            cpa16(sb + FYW_OFF + (uint32_t)(r*OP_ST + seg*8)*2,
                  g_WoutH + (size_t)r*HH + seg*8);
        }
        asm volatile("cp.async.commit_group;" ::: "memory");
        asm volatile("cp.async.wait_group 0;" ::: "memory");
        __syncthreads();

        // warp = (mt, nh): rows mt*16..+16, cols nh*16..+16
        const int mt = warp >> 1;
        const int nh = warp & 1;
        const int aRow  = mt*16 + (lane & 15);
        const int aKoff = (lane >> 4) * 8;
        const int bRow  = nh*16 + (lane >> 4) * 8 + (lane & 7);
        const int bKoff = ((lane >> 3) & 1) * 8;

        float acc[2][4];
#pragma unroll
        for (int nt = 0; nt < 2; nt++)
#pragma unroll
            for (int q = 0; q < 4; q++) acc[nt][q] = 0.f;

#pragma unroll
        for (int ks = 0; ks < 16; ks++) {
            uint32_t ah[4], bh[4];
            ldm4(ah, sb + FYA_OFF + (uint32_t)(aRow*OP_ST + ks*16 + aKoff)*2);
            ldm4(bh, sb + FYW_OFF + (uint32_t)(bRow*OP_ST + ks*16 + bKoff)*2);
#pragma unroll
            for (int nt = 0; nt < 2; nt++)
                mma16816(acc[nt], ah, &bh[nt*2]);
        }

        const int rl = mt*16 + (lane >> 2);
        const int cb = (lane & 3) * 2;
#pragma unroll
        for (int nt = 0; nt < 2; nt++) {
            int col = nh*16 + nt*8 + cb;               // even, 0..30
            float b0 = bout[col];
            size_t base0 = (size_t)(row0 + rl) * YSTRIDE + (size_t)(step - 1) * OUT_;
            size_t base1 = base0 + 8u * YSTRIDE;
            y[base0 + col] = acc[nt][0] + b0;
            y[base1 + col] = acc[nt][2] + b0;
            if (col < 30) {
                float b1 = bout[col + 1];
                y[base0 + col + 1] = acc[nt][1] + b1;
                y[base1 + col + 1] = acc[nt][3] + b1;
            }
        }
        return;
    }

    // ---------- gru GEMM block ----------
    const int wm   = warp >> 3;        // 0..1  -> m offset wm*64
    const int wn   = warp & 7;         // 0..7  -> hidden col chunk wn*8
    const int col0 = blockIdx.y * 64;

    const int aRow  = wm*64 + (lane & 15);
    const int aKoff = (lane >> 4) * 8;

    const int lg = lane >> 3, lr = lane & 7;
    const int bRowOff = (((lg >> 1) * 64) + wn*8 + lr) * ST + (lg & 1) * 8;

    const int ar = tid >> 2, aseg = tid & 3;

    float acc[4][4][4];   // [mt][gate][q]
#pragma unroll
    for (int mt = 0; mt < 4; mt++)
#pragma unroll
        for (int g = 0; g < 4; g++)
#pragma unroll
            for (int q = 0; q < 4; q++) acc[mt][g][q] = 0.f;

    auto load_stage = [&](int s, uint32_t bufoff) {
        const int kb = s * 32;
        {
            uint32_t d = sb + bufoff + A_OFF + (uint32_t)(ar*ST + aseg*8) * 2;
            size_t go = (size_t)(row0 + ar) * HH + kb + aseg*8;
            cpa16(d, Ah + go);
        }
#pragma unroll
        for (int i = 0; i < 2; i++) {
            int e = tid + i * 512;
            int n = e >> 2, seg = e & 3;
            int j = ((n >> 6) << 8) + col0 + (n & 63);
            uint32_t d = sb + bufoff + (uint32_t)(n*ST + seg*8) * 2;
            size_t go = (size_t)j * HH + kb + seg*8;
            cpa16(d + BHI_OFF, Whi + go);
            cpa16(d + BLO_OFF, Wlo + go);
        }
    };

    load_stage(0, 0);
    asm volatile("cp.async.commit_group;" ::: "memory");

    for (int s = 0; s < 8; s++) {
        asm volatile("cp.async.wait_group 0;" ::: "memory");
        __syncthreads();
        if (s < 7) {
            load_stage(s + 1, ((s + 1) & 1) * BUFB);
            asm volatile("cp.async.commit_group;" ::: "memory");
        }
        const uint32_t base = sb + (s & 1) * BUFB;

#pragma unroll
        for (int kc = 0; kc < 2; kc++) {
            uint32_t bh[8], bl[8];
            {
                uint32_t a0 = base + BHI_OFF + (uint32_t)(bRowOff + kc*16) * 2;
                uint32_t a1 = a0 + (uint32_t)(128*ST) * 2;   // gates 2,3
                ldm4(&bh[0], a0);
                ldm4(&bh[4], a1);
                ldm4(&bl[0], a0 + (BLO_OFF - BHI_OFF));
                ldm4(&bl[4], a1 + (BLO_OFF - BHI_OFF));
            }
#pragma unroll
            for (int mt = 0; mt < 4; mt++) {
                uint32_t aaddr = base + A_OFF +
                    (uint32_t)((aRow + mt*16)*ST + kc*16 + aKoff) * 2;
                uint32_t ah[4];
                ldm4(ah, aaddr);
#pragma unroll
                for (int g = 0; g < 4; g++) {
                    mma16816(acc[mt][g], ah, &bh[g*2]);
                    mma16816(acc[mt][g], ah, &bl[g*2]);
                }
            }
        }
    }

    // ---- in-register epilogue ----
    const int cA = wn*8 + (lane & 3)*2;
    const int cg = col0 + cA;
    const float2 br = *(const float2*)&g_b4[cg];
    const float2 bz = *(const float2*)&g_b4[256 + cg];
    const float2 bn = *(const float2*)&g_b4[512 + cg];
    const float2 bm = *(const float2*)&g_b4[768 + cg];
    const float bias[4][2] = {{br.x,br.y},{bz.x,bz.y},{bn.x,bn.y},{bm.x,bm.y}};

#pragma unroll
    for (int mt = 0; mt < 4; mt++) {
        const int rr = row0 + wm*64 + mt*16 + (lane >> 2);
#pragma unroll
        for (int p = 0; p < 2; p++) {
            const int r = rr + p*8;
            float2 hp = *(const float2*)(hprev + (size_t)r*HH + cg);
            float hpv[2] = {hp.x, hp.y};
            float hn[2];
#pragma unroll
            for (int j = 0; j < 2; j++) {
                int q = p*2 + j;
                float arv = acc[mt][0][q] + bias[0][j];
                float azv = acc[mt][1][q] + bias[1][j];
                float anv = acc[mt][2][q] + bias[2][j];
                float ahv = acc[mt][3][q] + bias[3][j];
                float rg = 1.f / (1.f + __expf(-arv));
                float zg = 1.f / (1.f + __expf(-azv));
                float x  = anv + rg * ahv;
                float t  = __expf(-2.f * fabsf(x));
                float th = (1.f - t) / (1.f + t);
                th = copysignf(th, x);
                hn[j] = (1.f - zg) * th + zg * hpv[j];
            }
            *(float2*)(hout + (size_t)r*HH + cg) = make_float2(hn[0], hn[1]);
            __half2 h2 = __floats2half2_rn(hn[0], hn[1]);
            *(__half2*)(Oh + (size_t)r*HH + cg) = h2;
        }
    }
}

// ---------------- standalone final out_proj: M=64/CTA, block=128 (R8 shape) ----------------
__global__ void __launch_bounds__(128)
out_proj_kernel(const __half* __restrict__ Ah, const float* __restrict__ bout,
                float* __restrict__ y, int step)
{
    extern __shared__ __align__(16) char dsm[];
    const uint32_t sb = smem_u32(dsm);

    const int tid  = threadIdx.x;
    const int lane = tid & 31;
    const int warp = tid >> 5;
    const int row0 = blockIdx.x * 64;

#pragma unroll
    for (int i = 0; i < 16; i++) {
        int e = tid + i * 128;
        int r = e >> 5, seg = e & 31;
        cpa16(sb + OPA_OFF + (uint32_t)(r*OP_ST + seg*8)*2,
              Ah + (size_t)(row0 + r)*HH + seg*8);
    }
#pragma unroll
    for (int i = 0; i < 8; i++) {
        int e = tid + i * 128;
        int r = e >> 5, seg = e & 31;
        cpa16(sb + OPW_OFF + (uint32_t)(r*OP_ST + seg*8)*2,
              g_WoutH + (size_t)r*HH + seg*8);
    }
    asm volatile("cp.async.commit_group;" ::: "memory");
    asm volatile("cp.async.wait_group 0;" ::: "memory");
    __syncthreads();

    const int aRow  = warp*16 + (lane & 15);
    const int aKoff = (lane >> 4) * 8;
    const int bRow  = (lane >> 4) * 8 + (lane & 7);
    const int bKoff = ((lane >> 3) & 1) * 8;

    float acc[4][4];
#pragma unroll
    for (int nt = 0; nt < 4; nt++)
#pragma unroll
        for (int q = 0; q < 4; q++) acc[nt][q] = 0.f;

#pragma unroll
    for (int ks = 0; ks < 16; ks++) {
        uint32_t ah[4], bh[8];
        ldm4(ah, sb + OPA_OFF + (uint32_t)(aRow*OP_ST + ks*16 + aKoff)*2);
#pragma unroll
        for (int p = 0; p < 2; p++)
            ldm4(&bh[p*4], sb + OPW_OFF + (uint32_t)((bRow + p*16)*OP_ST + ks*16 + bKoff)*2);
#pragma unroll
        for (int nt = 0; nt < 4; nt++)
            mma16816(acc[nt], ah, &bh[nt*2]);
    }

    const int rl  = warp*16 + (lane >> 2);
    const int cb  = (lane & 3) * 2;
#pragma unroll
    for (int nt = 0; nt < 4; nt++) {
        int col = nt*8 + cb;
        float b0 = bout[col];
        size_t base0 = (size_t)(row0 + rl) * YSTRIDE + (size_t)step * OUT_;
        size_t base1 = base0 + 8u * YSTRIDE;
        y[base0 + col] = acc[nt][0] + b0;
        y[base1 + col] = acc[nt][2] + b0;
        if (col < 30) {
            float b1 = bout[col + 1];
            y[base0 + col + 1] = acc[nt][1] + b1;
            y[base1 + col + 1] = acc[nt][3] + b1;
        }
    }
}

// ---------------- host ----------------
extern "C" void kernel_launch(void* const* d_in, const int* in_sizes, int n_in,
                              void* d_out, int out_size)
{
    const float* hidden = (const float*)d_in[0];
    const float* Wih    = (const float*)d_in[1];
    const float* Whh    = (const float*)d_in[2];
    const float* bih    = (const float*)d_in[3];
    const float* bhh    = (const float*)d_in[4];
    const float* Wout   = (const float*)d_in[5];
    const float* bout   = (const float*)d_in[6];
    float* y = (float*)d_out;

    __half *pWhi, *pWlo, *pWhi0, *pWlo0, *ps0, *ps1;
    float *phA, *phB;
    cudaGetSymbolAddress((void**)&pWhi,  g_Whi);
    cudaGetSymbolAddress((void**)&pWlo,  g_Wlo);
    cudaGetSymbolAddress((void**)&pWhi0, g_Whi0);
    cudaGetSymbolAddress((void**)&pWlo0, g_Wlo0);
    cudaGetSymbolAddress((void**)&ps0,   g_s0);
    cudaGetSymbolAddress((void**)&ps1,   g_s1);
    cudaGetSymbolAddress((void**)&phA,   g_hA);
    cudaGetSymbolAddress((void**)&phB,   g_hB);

    cudaFuncSetAttribute(gru_mma_kernel, cudaFuncAttributeMaxDynamicSharedMemorySize, SMEM_ALLOC);
    cudaFuncSetAttribute(out_proj_kernel, cudaFuncAttributeMaxDynamicSharedMemorySize, OP_SMEM);

    prep_kernel<<<(4*HH*HH + 255)/256, 256>>>(Wih, Whh, bih, bhh, Wout);
    split_kernel<<<(BB*HH + 255)/256, 256>>>(hidden, ps0);

    dim3 grid(BB/128, 5);   // (128, 4 gru slices + 1 y-projection slice)

    // step 0: x=0 variant; y-slice skips (step==0)
    gru_mma_kernel<<<grid, 512, SMEM_ALLOC>>>(ps0, pWhi0, pWlo0, hidden, phA, ps1,
                                              bout, y, 0);

    float* hin = phA;  float* hot = phB;
    __half *ih = ps1, *oh = ps0;

    for (int t = 1; t < STEPS; t++) {
        // y-slice computes y_{t-1} from ih; gru slices compute h_t
        gru_mma_kernel<<<grid, 512, SMEM_ALLOC>>>(ih, pWhi, pWlo, hin, hot, oh,
                                                  bout, y, t);
        float* tf = hin; hin = hot; hot = tf;
        __half* th = ih; ih = oh; oh = th;
    }
    // y_119 from final state (in `ih` after last swap)
    out_proj_kernel<<<BB/64, 128, OP_SMEM>>>(ih, bout, y, STEPS - 1);
}

// round 12
// speedup vs baseline: 3.5533x; 1.0642x over previous
#include <cuda_runtime.h>
#include <cuda_fp16.h>
#include <math.h>
#include <stdint.h>

#define BB 16384
#define HH 256
#define STEPS 120
#define OUT_ 31
#define YSTRIDE (STEPS*OUT_)

// ---- gru GEMM tiling: CTA = 64 rows x 256 gate cols (4 gates x 64 hidden cols) ----
#define ST   40            // smem row stride in halves (32 data + 8 pad)
#define A_OFF   0u
#define BHI_OFF 5120u      // A stage = 64*40*2 = 5120 B
#define BLO_OFF 25600u     // Bhi = 256*40*2 = 20480 B
#define BUFB    46080u     // stage total
#define SMEM_ALLOC 92160   // 2 stages; 2 CTAs/SM = 184 KB <= 227 KB

// ---- fused y-projection (blockIdx.y==4): M=64, N=32, K=256 ----
#define OP_ST 264          // halves per smem row (256 + 8 pad)
#define FYA_OFF 0u
#define FYW_OFF 33792u     // A = 64*264*2; + W 32*264*2 = 16896 -> 50688 <= SMEM_ALLOC

// ---- standalone final out_proj: M=64/CTA, block=128 ----
#define OPA_OFF 0u
#define OPW_OFF 33792u
#define OP_SMEM 50688u

// ---------------- device scratch (no allocs allowed) ----------------
__device__ __half g_Whi [4*HH*HH];
__device__ __half g_Wlo [4*HH*HH];
__device__ __half g_Whi0[4*HH*HH];
__device__ __half g_Wlo0[4*HH*HH];
__device__ __half g_WoutH[32*HH];    // fp16 Wout, row 31 zero-padded
__device__ float g_b4[4*HH];
__device__ float g_hA[BB*HH];
__device__ float g_hB[BB*HH];
__device__ __half g_s0[BB*HH], g_s1[BB*HH];

// ---------------- PTX helpers (family-safe: sm_80-era only) ----------------
__device__ __forceinline__ uint32_t smem_u32(const void* p) {
    uint32_t a;
    asm("{ .reg .u64 t; cvta.to.shared.u64 t, %1; cvt.u32.u64 %0, t; }" : "=r"(a) : "l"(p));
    return a;
}
__device__ __forceinline__ void cpa16(uint32_t dst, const void* src) {
    asm volatile("cp.async.cg.shared.global [%0], [%1], 16;" :: "r"(dst), "l"(src) : "memory");
}
__device__ __forceinline__ void ldm4(uint32_t* r, uint32_t addr) {
    asm volatile("ldmatrix.sync.aligned.m8n8.x4.shared.b16 {%0,%1,%2,%3}, [%4];"
                 : "=r"(r[0]), "=r"(r[1]), "=r"(r[2]), "=r"(r[3]) : "r"(addr));
}
__device__ __forceinline__ void mma16816(float* c, const uint32_t* a, const uint32_t* b) {
    asm volatile("mma.sync.aligned.m16n8k16.row.col.f32.f16.f16.f32 "
                 "{%0,%1,%2,%3}, {%4,%5,%6,%7}, {%8,%9}, {%0,%1,%2,%3};"
                 : "+f"(c[0]), "+f"(c[1]), "+f"(c[2]), "+f"(c[3])
                 : "r"(a[0]), "r"(a[1]), "r"(a[2]), "r"(a[3]), "r"(b[0]), "r"(b[1]));
}

// ---------------- prep ----------------
__global__ void prep_kernel(const float* __restrict__ Wih, const float* __restrict__ Whh,
                            const float* __restrict__ bih, const float* __restrict__ bhh,
                            const float* __restrict__ Wout)
{
    int idx = blockIdx.x * blockDim.x + threadIdx.x;
    if (idx < 4*HH*HH) {
        int j = idx / HH;
        int k = idx % HH;
        int g = j >> 8, c = j & 255;
        float w, w0;
        if (g == 0)      { float a = Wih[c*HH+k],       b = Whh[c*HH+k];       w = a + b; w0 = b; }
        else if (g == 1) { float a = Wih[(256+c)*HH+k], b = Whh[(256+c)*HH+k]; w = a + b; w0 = b; }
        else if (g == 2) { w = Wih[(512+c)*HH+k]; w0 = 0.f; }
        else             { w = Whh[(512+c)*HH+k]; w0 = w;  }
        __half hi = __float2half_rn(w);
        g_Whi[idx] = hi;
        g_Wlo[idx] = __float2half_rn(w - __half2float(hi));
        __half hi0 = __float2half_rn(w0);
        g_Whi0[idx] = hi0;
        g_Wlo0[idx] = __float2half_rn(w0 - __half2float(hi0));
    }
    if (idx < 32*HH) {
        int o = idx >> 8, k = idx & 255;
        g_WoutH[idx] = __float2half_rn(o < OUT_ ? Wout[o*HH + k] : 0.f);
    }
    if (idx < 4*HH) {
        int g = idx >> 8, c = idx & 255;
        float b;
        if (g == 0)      b = bih[c]     + bhh[c];
        else if (g == 1) b = bih[256+c] + bhh[256+c];
        else if (g == 2) b = bih[512+c];
        else             b = bhh[512+c];
        g_b4[idx] = b;
    }
}

__global__ void split_kernel(const float* __restrict__ h, __half* __restrict__ o)
{
    int idx = blockIdx.x * blockDim.x + threadIdx.x;
    if (idx < BB*HH) o[idx] = __float2half_rn(h[idx]);
}

// ---------------- fused GRU step + previous-step y projection ----------------
// grid = (256, 5), 256 threads (8 warps), 2 CTAs/SM.
//   blockIdx.y < 4 : gru GEMM (rows bx*64, hidden cols by*64), gate-interleaved warps
//   blockIdx.y == 4: y_{step-1} = Ah @ Wout^T + bout (skipped when step==0)
__global__ void __launch_bounds__(256, 2)
gru_mma_kernel(const __half* __restrict__ Ah,
               const __half* __restrict__ Whi, const __half* __restrict__ Wlo,
               const float* __restrict__ hprev, float* __restrict__ hout,
               __half* __restrict__ Oh,
               const float* __restrict__ bout, float* __restrict__ y, int step)
{
    extern __shared__ __align__(16) char dsm[];
    const uint32_t sb = smem_u32(dsm);

    const int tid  = threadIdx.x;
    const int lane = tid & 31;
    const int warp = tid >> 5;
    const int row0 = blockIdx.x * 64;

    if (blockIdx.y == 4) {
        // ---------- y-projection block: M=64, N=32, K=256 ----------
        if (step == 0) return;
        // load A: 64 rows x 256 halves = 2048 x 16B chunks, 8/thread
#pragma unroll
        for (int i = 0; i < 8; i++) {
            int e = tid + i * 256;
            int r = e >> 5, seg = e & 31;
            cpa16(sb + FYA_OFF + (uint32_t)(r*OP_ST + seg*8)*2,
                  Ah + (size_t)(row0 + r)*HH + seg*8);
        }
        // load W: 32 rows x 256 halves = 1024 chunks, 4/thread
#pragma unroll
        for (int i = 0; i < 4; i++) {
            int e = tid + i * 256;
            int r = e >> 5, seg = e & 31;
            cpa16(sb + FYW_OFF + (uint32_t)(r*OP_ST + seg*8)*2,
                  g_WoutH + (size_t)r*HH + seg*8);
        }
        asm volatile("cp.async.commit_group;" ::: "memory");
        asm volatile("cp.async.wait_group 0;" ::: "memory");
        __syncthreads();

        // warp = (mt 0..3, nh 0..1): rows mt*16..+16, cols nh*16..+16
        const int mt = warp >> 1;
        const int nh = warp & 1;
        const int aRow  = mt*16 + (lane & 15);
        const int aKoff = (lane >> 4) * 8;
        const int bRow  = nh*16 + (lane >> 4) * 8 + (lane & 7);
        const int bKoff = ((lane >> 3) & 1) * 8;

        float acc[2][4];
#pragma unroll
        for (int nt = 0; nt < 2; nt++)
#pragma unroll
            for (int q = 0; q < 4; q++) acc[nt][q] = 0.f;

#pragma unroll
        for (int ks = 0; ks < 16; ks++) {
            uint32_t ah[4], bh[4];
            ldm4(ah, sb + FYA_OFF + (uint32_t)(aRow*OP_ST + ks*16 + aKoff)*2);
            ldm4(bh, sb + FYW_OFF + (uint32_t)(bRow*OP_ST + ks*16 + bKoff)*2);
#pragma unroll
            for (int nt = 0; nt < 2; nt++)
                mma16816(acc[nt], ah, &bh[nt*2]);
        }

        const int rl = mt*16 + (lane >> 2);
        const int cb = (lane & 3) * 2;
#pragma unroll
        for (int nt = 0; nt < 2; nt++) {
            int col = nh*16 + nt*8 + cb;               // even, 0..30
            float b0 = bout[col];
            size_t base0 = (size_t)(row0 + rl) * YSTRIDE + (size_t)(step - 1) * OUT_;
            size_t base1 = base0 + 8u * YSTRIDE;
            y[base0 + col] = acc[nt][0] + b0;
            y[base1 + col] = acc[nt][2] + b0;
            if (col < 30) {
                float b1 = bout[col + 1];
                y[base0 + col + 1] = acc[nt][1] + b1;
                y[base1 + col + 1] = acc[nt][3] + b1;
            }
        }
        return;
    }

    // ---------- gru GEMM block: 64 rows, 8 warps = 8 hidden-col chunks ----------
    const int wn   = warp;             // 0..7 -> hidden col chunk wn*8
    const int col0 = blockIdx.y * 64;

    const int aRow  = lane & 15;
    const int aKoff = (lane >> 4) * 8;

    const int lg = lane >> 3, lr = lane & 7;
    const int bRowOff = (((lg >> 1) * 64) + wn*8 + lr) * ST + (lg & 1) * 8;

    const int ar = tid >> 2, aseg = tid & 3;   // A: 256 x 16B chunks, 1/thread

    float acc[4][4][4];   // [mt][gate][q]
#pragma unroll
    for (int mt = 0; mt < 4; mt++)
#pragma unroll
        for (int g = 0; g < 4; g++)
#pragma unroll
            for (int q = 0; q < 4; q++) acc[mt][g][q] = 0.f;

    auto load_stage = [&](int s, uint32_t bufoff) {
        const int kb = s * 32;
        {
            uint32_t d = sb + bufoff + A_OFF + (uint32_t)(ar*ST + aseg*8) * 2;
            size_t go = (size_t)(row0 + ar) * HH + kb + aseg*8;
            cpa16(d, Ah + go);
        }
#pragma unroll
        for (int i = 0; i < 4; i++) {
            int e = tid + i * 256;
            int n = e >> 2, seg = e & 3;
            int j = ((n >> 6) << 8) + col0 + (n & 63);
            uint32_t d = sb + bufoff + (uint32_t)(n*ST + seg*8) * 2;
            size_t go = (size_t)j * HH + kb + seg*8;
            cpa16(d + BHI_OFF, Whi + go);
            cpa16(d + BLO_OFF, Wlo + go);
        }
    };

    load_stage(0, 0);
    asm volatile("cp.async.commit_group;" ::: "memory");

    for (int s = 0; s < 8; s++) {
        asm volatile("cp.async.wait_group 0;" ::: "memory");
        __syncthreads();
        if (s < 7) {
            load_stage(s + 1, ((s + 1) & 1) * BUFB);
            asm volatile("cp.async.commit_group;" ::: "memory");
        }
        const uint32_t base = sb + (s & 1) * BUFB;

#pragma unroll
        for (int kc = 0; kc < 2; kc++) {
            uint32_t bh[8], bl[8];
            {
                uint32_t a0 = base + BHI_OFF + (uint32_t)(bRowOff + kc*16) * 2;
                uint32_t a1 = a0 + (uint32_t)(128*ST) * 2;   // gates 2,3
                ldm4(&bh[0], a0);
                ldm4(&bh[4], a1);
                ldm4(&bl[0], a0 + (BLO_OFF - BHI_OFF));
                ldm4(&bl[4], a1 + (BLO_OFF - BHI_OFF));
            }
#pragma unroll
            for (int mt = 0; mt < 4; mt++) {
                uint32_t aaddr = base + A_OFF +
                    (uint32_t)((aRow + mt*16)*ST + kc*16 + aKoff) * 2;
                uint32_t ah[4];
                ldm4(ah, aaddr);
#pragma unroll
                for (int g = 0; g < 4; g++) {
                    mma16816(acc[mt][g], ah, &bh[g*2]);
                    mma16816(acc[mt][g], ah, &bl[g*2]);
                }
            }
        }
    }

    // ---- in-register epilogue ----
    const int cA = wn*8 + (lane & 3)*2;
    const int cg = col0 + cA;
    const float2 br = *(const float2*)&g_b4[cg];
    const float2 bz = *(const float2*)&g_b4[256 + cg];
    const float2 bn = *(const float2*)&g_b4[512 + cg];
    const float2 bm = *(const float2*)&g_b4[768 + cg];
    const float bias[4][2] = {{br.x,br.y},{bz.x,bz.y},{bn.x,bn.y},{bm.x,bm.y}};

#pragma unroll
    for (int mt = 0; mt < 4; mt++) {
        const int rr = row0 + mt*16 + (lane >> 2);
#pragma unroll
        for (int p = 0; p < 2; p++) {
            const int r = rr + p*8;
            float2 hp = *(const float2*)(hprev + (size_t)r*HH + cg);
            float hpv[2] = {hp.x, hp.y};
            float hn[2];
#pragma unroll
            for (int j = 0; j < 2; j++) {
                int q = p*2 + j;
                float arv = acc[mt][0][q] + bias[0][j];
                float azv = acc[mt][1][q] + bias[1][j];
                float anv = acc[mt][2][q] + bias[2][j];
                float ahv = acc[mt][3][q] + bias[3][j];
                float rg = 1.f / (1.f + __expf(-arv));
                float zg = 1.f / (1.f + __expf(-azv));
                float x  = anv + rg * ahv;
                float t  = __expf(-2.f * fabsf(x));
                float th = (1.f - t) / (1.f + t);
                th = copysignf(th, x);
                hn[j] = (1.f - zg) * th + zg * hpv[j];
            }
            *(float2*)(hout + (size_t)r*HH + cg) = make_float2(hn[0], hn[1]);
            __half2 h2 = __floats2half2_rn(hn[0], hn[1]);
            *(__half2*)(Oh + (size_t)r*HH + cg) = h2;
        }
    }
}

// ---------------- standalone final out_proj: M=64/CTA, block=128 (R8 shape) ----------------
__global__ void __launch_bounds__(128)
out_proj_kernel(const __half* __restrict__ Ah, const float* __restrict__ bout,
                float* __restrict__ y, int step)
{
    extern __shared__ __align__(16) char dsm[];
    const uint32_t sb = smem_u32(dsm);

    const int tid  = threadIdx.x;
    const int lane = tid & 31;
    const int warp = tid >> 5;
    const int row0 = blockIdx.x * 64;

#pragma unroll
    for (int i = 0; i < 16; i++) {
        int e = tid + i * 128;
        int r = e >> 5, seg = e & 31;
        cpa16(sb + OPA_OFF + (uint32_t)(r*OP_ST + seg*8)*2,
              Ah + (size_t)(row0 + r)*HH + seg*8);
    }
#pragma unroll
    for (int i = 0; i < 8; i++) {
        int e = tid + i * 128;
        int r = e >> 5, seg = e & 31;
        cpa16(sb + OPW_OFF + (uint32_t)(r*OP_ST + seg*8)*2,
              g_WoutH + (size_t)r*HH + seg*8);
    }
    asm volatile("cp.async.commit_group;" ::: "memory");
    asm volatile("cp.async.wait_group 0;" ::: "memory");
    __syncthreads();

    const int aRow  = warp*16 + (lane & 15);
    const int aKoff = (lane >> 4) * 8;
    const int bRow  = (lane >> 4) * 8 + (lane & 7);
    const int bKoff = ((lane >> 3) & 1) * 8;

    float acc[4][4];
#pragma unroll
    for (int nt = 0; nt < 4; nt++)
#pragma unroll
        for (int q = 0; q < 4; q++) acc[nt][q] = 0.f;

#pragma unroll
    for (int ks = 0; ks < 16; ks++) {
        uint32_t ah[4], bh[8];
        ldm4(ah, sb + OPA_OFF + (uint32_t)(aRow*OP_ST + ks*16 + aKoff)*2);
#pragma unroll
        for (int p = 0; p < 2; p++)
            ldm4(&bh[p*4], sb + OPW_OFF + (uint32_t)((bRow + p*16)*OP_ST + ks*16 + bKoff)*2);
#pragma unroll
        for (int nt = 0; nt < 4; nt++)
            mma16816(acc[nt], ah, &bh[nt*2]);
    }

    const int rl  = warp*16 + (lane >> 2);
    const int cb  = (lane & 3) * 2;
#pragma unroll
    for (int nt = 0; nt < 4; nt++) {
        int col = nt*8 + cb;
        float b0 = bout[col];
        size_t base0 = (size_t)(row0 + rl) * YSTRIDE + (size_t)step * OUT_;
        size_t base1 = base0 + 8u * YSTRIDE;
        y[base0 + col] = acc[nt][0] + b0;
        y[base1 + col] = acc[nt][2] + b0;
        if (col < 30) {
            float b1 = bout[col + 1];
            y[base0 + col + 1] = acc[nt][1] + b1;
            y[base1 + col + 1] = acc[nt][3] + b1;
        }
    }
}

// ---------------- host ----------------
extern "C" void kernel_launch(void* const* d_in, const int* in_sizes, int n_in,
                              void* d_out, int out_size)
{
    const float* hidden = (const float*)d_in[0];
    const float* Wih    = (const float*)d_in[1];
    const float* Whh    = (const float*)d_in[2];
    const float* bih    = (const float*)d_in[3];
    const float* bhh    = (const float*)d_in[4];
    const float* Wout   = (const float*)d_in[5];
    const float* bout   = (const float*)d_in[6];
    float* y = (float*)d_out;

    __half *pWhi, *pWlo, *pWhi0, *pWlo0, *ps0, *ps1;
    float *phA, *phB;
    cudaGetSymbolAddress((void**)&pWhi,  g_Whi);
    cudaGetSymbolAddress((void**)&pWlo,  g_Wlo);
    cudaGetSymbolAddress((void**)&pWhi0, g_Whi0);
    cudaGetSymbolAddress((void**)&pWlo0, g_Wlo0);
    cudaGetSymbolAddress((void**)&ps0,   g_s0);
    cudaGetSymbolAddress((void**)&ps1,   g_s1);
    cudaGetSymbolAddress((void**)&phA,   g_hA);
    cudaGetSymbolAddress((void**)&phB,   g_hB);

    cudaFuncSetAttribute(gru_mma_kernel, cudaFuncAttributeMaxDynamicSharedMemorySize, SMEM_ALLOC);
    cudaFuncSetAttribute(out_proj_kernel, cudaFuncAttributeMaxDynamicSharedMemorySize, OP_SMEM);

    prep_kernel<<<(4*HH*HH + 255)/256, 256>>>(Wih, Whh, bih, bhh, Wout);
    split_kernel<<<(BB*HH + 255)/256, 256>>>(hidden, ps0);

    dim3 grid(BB/64, 5);   // (256, 4 gru slices + 1 y-projection slice)

    // step 0: x=0 variant; y-slice skips (step==0)
    gru_mma_kernel<<<grid, 256, SMEM_ALLOC>>>(ps0, pWhi0, pWlo0, hidden, phA, ps1,
                                              bout, y, 0);

    float* hin = phA;  float* hot = phB;
    __half *ih = ps1, *oh = ps0;

    for (int t = 1; t < STEPS; t++) {
        // y-slice computes y_{t-1} from ih; gru slices compute h_t
        gru_mma_kernel<<<grid, 256, SMEM_ALLOC>>>(ih, pWhi, pWlo, hin, hot, oh,
                                                  bout, y, t);
        float* tf = hin; hin = hot; hot = tf;
        __half* th = ih; ih = oh; oh = th;
    }
    // y_119 from final state (in `ih` after last swap)
    out_proj_kernel<<<BB/64, 128, OP_SMEM>>>(ih, bout, y, STEPS - 1);
}